// round 13
// baseline (speedup 1.0000x reference)
#include <cuda_runtime.h>
#include <cstdint>

// Problem constants
#define NLAYERS 12
#define BATCH   4
#define SEQ     1024
#define DMODEL  512
#define NHEADS  8
#define DHEAD   64
#define FDIM    2048
#define MROWS   (BATCH*SEQ)   // 4096

// ===========================================================================
// sm_80-level PTX helpers
// ===========================================================================
#define CP_ASYNC16(dst, src) \
    asm volatile("cp.async.cg.shared.global [%0], [%1], 16;" :: "r"(dst), "l"(src))
#define CP_COMMIT() asm volatile("cp.async.commit_group;" ::: "memory")
#define CP_WAIT0()  asm volatile("cp.async.wait_group 0;" ::: "memory")
#define CP_WAIT1()  asm volatile("cp.async.wait_group 1;" ::: "memory")

__device__ __forceinline__ void tf32_split(float x, uint32_t& hi, uint32_t& lo) {
    uint32_t h;
    asm("cvt.rna.tf32.f32 %0, %1;" : "=r"(h) : "f"(x));
    float r = x - __uint_as_float(h);
    uint32_t l;
    asm("cvt.rna.tf32.f32 %0, %1;" : "=r"(l) : "f"(r));
    hi = h; lo = l;
}

// Split two fp32 (k-adjacent pair) into packed bf16x2 hi and lo parts.
__device__ __forceinline__ void bf16_split2(float x0, float x1,
                                            uint32_t& hi, uint32_t& lo) {
    uint32_t h;
    asm("cvt.rn.bf16x2.f32 %0, %1, %2;" : "=r"(h) : "f"(x1), "f"(x0));
    float h0 = __uint_as_float(h << 16);
    float h1 = __uint_as_float(h & 0xffff0000u);
    float r0 = x0 - h0, r1 = x1 - h1;
    uint32_t l;
    asm("cvt.rn.bf16x2.f32 %0, %1, %2;" : "=r"(l) : "f"(r1), "f"(r0));
    hi = h; lo = l;
}

__device__ __forceinline__ void mma8(float* c, const uint32_t* a, const uint32_t* b) {
    asm volatile(
        "mma.sync.aligned.m16n8k8.row.col.f32.tf32.tf32.f32 "
        "{%0,%1,%2,%3}, {%4,%5,%6,%7}, {%8,%9}, {%0,%1,%2,%3};"
        : "+f"(c[0]), "+f"(c[1]), "+f"(c[2]), "+f"(c[3])
        : "r"(a[0]), "r"(a[1]), "r"(a[2]), "r"(a[3]), "r"(b[0]), "r"(b[1]));
}

__device__ __forceinline__ void mma16(float* c, const uint32_t* a, const uint32_t* b) {
    asm volatile(
        "mma.sync.aligned.m16n8k16.row.col.f32.bf16.bf16.f32 "
        "{%0,%1,%2,%3}, {%4,%5,%6,%7}, {%8,%9}, {%0,%1,%2,%3};"
        : "+f"(c[0]), "+f"(c[1]), "+f"(c[2]), "+f"(c[3])
        : "r"(a[0]), "r"(a[1]), "r"(a[2]), "r"(a[3]), "r"(b[0]), "r"(b[1]));
}

// ===========================================================================
// Scratch (static device globals; no allocation anywhere)
// ===========================================================================
__device__ float g_x[MROWS*DMODEL];
__device__ float g_qkv[3L*MROWS*DMODEL];     // q, k, v slabs
__device__ float g_y[MROWS*DMODEL];
__device__ float g_t[MROWS*DMODEL];
__device__ float g_f[MROWS*FDIM];
// tf32 pre-split weights [fam][layer][N][K] (hi/lo), fams: sq sk cq ck
__device__ uint32_t g_wthi[12582912];
__device__ uint32_t g_wtlo[12582912];
// bf16 pre-split weights, packed bf16x2 along K: [fam][layer][N][K/2]
// sv@0, so@12*131072, cv@24*.., co@36*.., f1@48*131072, f2@F1+12*524288
__device__ uint32_t g_whi[18874368];
__device__ uint32_t g_wlo[18874368];
__device__ float g_bias[4L*NLAYERS*DMODEL];  // packed biases (slots 0,1: sq, sk)

// ===========================================================================
// Setup kernels
// ===========================================================================
// Transpose + tf32-split 4 DxD families (z = 4*12). W[K][N] -> hi/lo [N][K].
__global__ void tsplit4t_k(const float* __restrict__ s0, const float* __restrict__ s1,
                           const float* __restrict__ s2, const float* __restrict__ s3,
                           uint32_t* __restrict__ dhi, uint32_t* __restrict__ dlo)
{
    __shared__ float tt[32][33];
    const int z = blockIdx.z;
    const int f = z / NLAYERS, ly = z % NLAYERS;
    const float* S = (f == 0) ? s0 : (f == 1) ? s1 : (f == 2) ? s2 : s3;
    const long DD = (long)DMODEL*DMODEL;
    S += (long)ly * DD;
    uint32_t* DH = dhi + (long)f*NLAYERS*DD + (long)ly*DD;
    uint32_t* DL = dlo + (long)f*NLAYERS*DD + (long)ly*DD;

    const int k0 = blockIdx.y * 32, n0 = blockIdx.x * 32;
    const int tx = threadIdx.x, ty = threadIdx.y;
    #pragma unroll
    for (int i = 0; i < 32; i += 8)
        tt[ty + i][tx] = S[(long)(k0 + ty + i)*DMODEL + n0 + tx];   // tt[k][n]
    __syncthreads();
    const int base = ty*32 + tx;
    #pragma unroll
    for (int q = 0; q < 4; q++) {
        const int o = base + q*256;
        const int nl = o >> 5, kl = o & 31;
        uint32_t h, l;
        tf32_split(tt[kl][nl], h, l);
        DH[(long)(n0 + nl)*DMODEL + k0 + kl] = h;
        DL[(long)(n0 + nl)*DMODEL + k0 + kl] = l;
    }
}

// Transpose + bf16-split 4 DxD bf16-path families (z = 4*12).
__global__ void tsplit4_k(const float* __restrict__ s0, const float* __restrict__ s1,
                          const float* __restrict__ s2, const float* __restrict__ s3,
                          uint32_t* __restrict__ dhi, uint32_t* __restrict__ dlo)
{
    __shared__ float tt[32][33];
    const int z = blockIdx.z;
    const int f = z / NLAYERS, ly = z % NLAYERS;
    const float* S = (f == 0) ? s0 : (f == 1) ? s1 : (f == 2) ? s2 : s3;
    S += (long)ly * DMODEL*DMODEL;
    const long obase = (long)f*NLAYERS*DMODEL*(DMODEL/2) + (long)ly*DMODEL*(DMODEL/2);
    uint32_t* DH = dhi + obase;
    uint32_t* DL = dlo + obase;

    const int k0 = blockIdx.y * 32, n0 = blockIdx.x * 32;
    const int tx = threadIdx.x, ty = threadIdx.y;
    #pragma unroll
    for (int i = 0; i < 32; i += 8)
        tt[ty + i][tx] = S[(long)(k0 + ty + i)*DMODEL + n0 + tx];
    __syncthreads();
    const int base = ty*32 + tx;
    #pragma unroll
    for (int q = 0; q < 2; q++) {
        const int o = base + q*256;
        const int nl = o >> 4, kkl = o & 15;
        uint32_t h, l;
        bf16_split2(tt[2*kkl][nl], tt[2*kkl + 1][nl], h, l);
        DH[(long)(n0 + nl)*(DMODEL/2) + (k0 >> 1) + kkl] = h;
        DL[(long)(n0 + nl)*(DMODEL/2) + (k0 >> 1) + kkl] = l;
    }
}

// Generic transpose+bf16-split (f1: R=512,C=2048; f2: R=2048,C=512)
__global__ void tsplit_k(const float* __restrict__ S, uint32_t* __restrict__ DH,
                         uint32_t* __restrict__ DL, int R, int C)
{
    __shared__ float tt[32][33];
    const long ly = blockIdx.z;
    S  += ly * (long)R * C;
    DH += ly * (long)C * (R/2);
    DL += ly * (long)C * (R/2);

    const int k0 = blockIdx.y * 32, n0 = blockIdx.x * 32;
    const int tx = threadIdx.x, ty = threadIdx.y;
    #pragma unroll
    for (int i = 0; i < 32; i += 8)
        tt[ty + i][tx] = S[(long)(k0 + ty + i)*C + n0 + tx];
    __syncthreads();
    const int base = ty*32 + tx;
    #pragma unroll
    for (int q = 0; q < 2; q++) {
        const int o = base + q*256;
        const int nl = o >> 4, kkl = o & 15;
        uint32_t h, l;
        bf16_split2(tt[2*kkl][nl], tt[2*kkl + 1][nl], h, l);
        DH[(long)(n0 + nl)*(R/2) + (k0 >> 1) + kkl] = h;
        DL[(long)(n0 + nl)*(R/2) + (k0 >> 1) + kkl] = l;
    }
}

__global__ void packbias_k(const float* __restrict__ a0, const float* __restrict__ a1,
                           const float* __restrict__ a2, const float* __restrict__ a3,
                           float* __restrict__ dst)
{
    const int i = blockIdx.x*256 + threadIdx.x;
    const int f = i / (NLAYERS*DMODEL), r = i % (NLAYERS*DMODEL);
    const float* s = (f == 0) ? a0 : (f == 1) ? a1 : (f == 2) ? a2 : a3;
    dst[i] = s[r];
}

// ===========================================================================
// tf32 GEMM v2 — B from pre-split tf32 weights (hi/lo [N][K] uint32),
// A split staged in SMEM per k-tile.
// SMEM floats: A 2x2560 | AH 2560 | AL 2560 | BH 2x2560 | BL 2x2560
//            = 20480 floats = 81920 B
// ===========================================================================
#define SMEM_D32 81920

template<bool BIAS>
__global__ __launch_bounds__(256, 1) void gemm_tf32_k(
    const float* __restrict__ A, const uint32_t* __restrict__ Whi,
    const uint32_t* __restrict__ Wlo, const float* __restrict__ bias,
    float* __restrict__ C, int K, int lda, int ldw, int ldc,
    long sBb, long sCb, long sbz)
{
    constexpr int AS = 20;

    const int row0 = blockIdx.y * 128;
    const int col0 = blockIdx.x * 128;
    const int zb = blockIdx.z;
    Whi += (long)zb*sBb;
    Wlo += (long)zb*sBb;
    C   += (long)zb*sCb;
    if (BIAS) bias += (long)zb*sbz;

    extern __shared__ float smf[];
    float*    Asm = smf;                          // 2 x 2560
    uint32_t* AH  = (uint32_t*)(smf + 5120);      // 2560
    uint32_t* AL  = (uint32_t*)(smf + 7680);      // 2560
    uint32_t* BH  = (uint32_t*)(smf + 10240);     // 2 x 2560
    uint32_t* BL  = (uint32_t*)(smf + 15360);     // 2 x 2560

    const int tid  = threadIdx.x;
    const int wid  = tid >> 5;
    const int lane = tid & 31;
    const int g = lane >> 2, t = lane & 3;
    const int wm = (wid >> 2) * 64;
    const int wn = (wid & 3) * 32;

    const int ns = K >> 4;

    auto loadA = [&](int s) {
        float* dst = Asm + (s & 1) * 2560;
        const int r  = tid >> 1;
        const int kc = (tid & 1) << 3;
        uint32_t d = (uint32_t)__cvta_generic_to_shared(dst + r*AS + kc);
        CP_ASYNC16(d, A + (long)(row0 + r)*lda + (s << 4) + kc);
        uint32_t d2 = (uint32_t)__cvta_generic_to_shared(dst + r*AS + kc + 4);
        CP_ASYNC16(d2, A + (long)(row0 + r)*lda + (s << 4) + kc + 4);
    };
    auto loadB = [&](int s) {
        uint32_t* dh = BH + (s & 1) * 2560;
        uint32_t* dl = BL + (s & 1) * 2560;
        const int r  = tid >> 1;
        const int kc = (tid & 1) << 3;
        uint32_t d = (uint32_t)__cvta_generic_to_shared(dh + r*AS + kc);
        CP_ASYNC16(d, Whi + (long)(col0 + r)*ldw + (s << 4) + kc);
        uint32_t d2 = (uint32_t)__cvta_generic_to_shared(dh + r*AS + kc + 4);
        CP_ASYNC16(d2, Whi + (long)(col0 + r)*ldw + (s << 4) + kc + 4);
        uint32_t d3 = (uint32_t)__cvta_generic_to_shared(dl + r*AS + kc);
        CP_ASYNC16(d3, Wlo + (long)(col0 + r)*ldw + (s << 4) + kc);
        uint32_t d4 = (uint32_t)__cvta_generic_to_shared(dl + r*AS + kc + 4);
        CP_ASYNC16(d4, Wlo + (long)(col0 + r)*ldw + (s << 4) + kc + 4);
    };

    float acc[4][4][4] = {};

    loadA(0); loadB(0); CP_COMMIT();

    for (int s = 0; s < ns; s++) {
        if (s + 1 < ns) { loadA(s+1); loadB(s+1); CP_COMMIT(); CP_WAIT1(); }
        else            { CP_WAIT0(); }
        __syncthreads();

        // --- stage A tf32-split: 128x16 fp32 -> AH/AL [128][16] (stride 20) ---
        {
            const float* a = Asm + (s & 1) * 2560;
            #pragma unroll
            for (int p2 = 0; p2 < 8; p2++) {
                const int p = tid + (p2 << 8);
                const int r = p >> 4, c = p & 15;
                uint32_t h, l;
                tf32_split(a[r*AS + c], h, l);
                AH[r*AS + c] = h;
                AL[r*AS + c] = l;
            }
        }
        __syncthreads();

        const uint32_t* bh = BH + (s & 1) * 2560;
        const uint32_t* bl = BL + (s & 1) * 2560;

        #pragma unroll
        for (int kk = 0; kk < 16; kk += 8) {
            uint32_t ahi[4][4], alo[4][4];
            #pragma unroll
            for (int i = 0; i < 4; i++) {
                const int m0 = wm + 16*i + g;
                ahi[i][0] = AH[(m0    )*AS + kk + t    ];
                ahi[i][1] = AH[(m0 + 8)*AS + kk + t    ];
                ahi[i][2] = AH[(m0    )*AS + kk + t + 4];
                ahi[i][3] = AH[(m0 + 8)*AS + kk + t + 4];
                alo[i][0] = AL[(m0    )*AS + kk + t    ];
                alo[i][1] = AL[(m0 + 8)*AS + kk + t    ];
                alo[i][2] = AL[(m0    )*AS + kk + t + 4];
                alo[i][3] = AL[(m0 + 8)*AS + kk + t + 4];
            }
            #pragma unroll
            for (int j = 0; j < 4; j++) {
                const int n0 = wn + 8*j + g;
                uint32_t bhi[2], blo[2];
                bhi[0] = bh[n0*AS + kk + t];    bhi[1] = bh[n0*AS + kk + t + 4];
                blo[0] = bl[n0*AS + kk + t];    blo[1] = bl[n0*AS + kk + t + 4];
                #pragma unroll
                for (int i = 0; i < 4; i++) {
                    mma8(acc[i][j], ahi[i], bhi);
                    mma8(acc[i][j], ahi[i], blo);
                    mma8(acc[i][j], alo[i], bhi);
                }
            }
        }
        __syncthreads();
    }

    #pragma unroll
    for (int j = 0; j < 4; j++) {
        const int cb = col0 + wn + 8*j + 2*t;
        float bx = 0.f, by = 0.f;
        if (BIAS) { bx = bias[cb]; by = bias[cb + 1]; }
        #pragma unroll
        for (int i = 0; i < 4; i++) {
            const int r = row0 + wm + 16*i + g;
            float2 v0, v1;
            v0.x = acc[i][j][0] + bx; v0.y = acc[i][j][1] + by;
            v1.x = acc[i][j][2] + bx; v1.y = acc[i][j][3] + by;
            *(float2*)&C[(long)r*ldc + cb]       = v0;
            *(float2*)&C[(long)(r + 8)*ldc + cb] = v1;
        }
    }
}

// ===========================================================================
// bf16 GEMM v2 — validated (round 11).
// ===========================================================================
#define SMEM_B16 57344

template<bool BIAS, bool RELU>
__global__ __launch_bounds__(256, 1) void gemm_bf16_k(
    const float* __restrict__ A, const uint32_t* __restrict__ Whi,
    const uint32_t* __restrict__ Wlo, const float* __restrict__ bias,
    float* __restrict__ C, int K, int lda, int ldw, int ldc)
{
    constexpr int AS = 20;
    constexpr int WS = 12;

    const int row0 = blockIdx.y * 128;
    const int col0 = blockIdx.x * 128;

    extern __shared__ float smf[];
    float*    Asm = smf;                          // 2 * 2560
    uint32_t* AH  = (uint32_t*)(smf + 5120);      // 1536
    uint32_t* AL  = (uint32_t*)(smf + 6656);      // 1536
    uint32_t* BH  = (uint32_t*)(smf + 8192);      // 2 * 1536
    uint32_t* BL  = (uint32_t*)(smf + 11264);     // 2 * 1536

    const int tid  = threadIdx.x;
    const int wid  = tid >> 5;
    const int lane = tid & 31;
    const int g = lane >> 2, t = lane & 3;
    const int wm = (wid >> 2) * 64;
    const int wn = (wid & 3) * 32;

    const int ns = K >> 4;

    auto loadA = [&](int s) {
        float* dst = Asm + (s & 1) * 2560;
        const int r  = tid >> 1;
        const int kc = (tid & 1) << 3;
        uint32_t d = (uint32_t)__cvta_generic_to_shared(dst + r*AS + kc);
        CP_ASYNC16(d, A + (long)(row0 + r)*lda + (s << 4) + kc);
        uint32_t d2 = (uint32_t)__cvta_generic_to_shared(dst + r*AS + kc + 4);
        CP_ASYNC16(d2, A + (long)(row0 + r)*lda + (s << 4) + kc + 4);
    };
    auto loadB = [&](int s) {
        uint32_t* dh = BH + (s & 1) * 1536;
        uint32_t* dl = BL + (s & 1) * 1536;
        const int r = tid >> 1, half = (tid & 1) << 2;
        uint32_t d = (uint32_t)__cvta_generic_to_shared(dh + r*WS + half);
        CP_ASYNC16(d, Whi + (long)(col0 + r)*ldw + (s << 3) + half);
        uint32_t d2 = (uint32_t)__cvta_generic_to_shared(dl + r*WS + half);
        CP_ASYNC16(d2, Wlo + (long)(col0 + r)*ldw + (s << 3) + half);
    };

    float acc[4][4][4] = {};

    loadA(0); loadB(0); CP_COMMIT();

    for (int s = 0; s < ns; s++) {
        if (s + 1 < ns) { loadA(s+1); loadB(s+1); CP_COMMIT(); CP_WAIT1(); }
        else            { CP_WAIT0(); }
        __syncthreads();

        {
            const float* a = Asm + (s & 1) * 2560;
            #pragma unroll
            for (int p2 = 0; p2 < 4; p2++) {
                const int p = tid + (p2 << 8);
                const int r = p >> 3, c2 = p & 7;
                float2 x = *(const float2*)&a[r*AS + 2*c2];
                uint32_t h, l;
                bf16_split2(x.x, x.y, h, l);
                AH[r*WS + c2] = h;
                AL[r*WS + c2] = l;
            }
        }
        __syncthreads();

        const uint32_t* bh = BH + (s & 1) * 1536;
        const uint32_t* bl = BL + (s & 1) * 1536;

        uint32_t ahi[4][4], alo[4][4];
        #pragma unroll
        for (int i = 0; i < 4; i++) {
            #pragma unroll
            for (int rr = 0; rr < 4; rr++) {
                const int r  = wm + 16*i + g + 8*(rr & 1);
                const int cc = t + 4*(rr >> 1);
                ahi[i][rr] = AH[r*WS + cc];
                alo[i][rr] = AL[r*WS + cc];
            }
        }
        #pragma unroll
        for (int j = 0; j < 4; j++) {
            const int n0 = wn + 8*j + g;
            uint32_t bhi[2], blo[2];
            bhi[0] = bh[n0*WS + t];     bhi[1] = bh[n0*WS + t + 4];
            blo[0] = bl[n0*WS + t];     blo[1] = bl[n0*WS + t + 4];
            #pragma unroll
            for (int i = 0; i < 4; i++) {
                mma16(acc[i][j], ahi[i], bhi);
                mma16(acc[i][j], ahi[i], blo);
                mma16(acc[i][j], alo[i], bhi);
            }
        }
        __syncthreads();
    }

    #pragma unroll
    for (int j = 0; j < 4; j++) {
        const int cb = col0 + wn + 8*j + 2*t;
        float bx = 0.f, by = 0.f;
        if (BIAS) { bx = bias[cb]; by = bias[cb + 1]; }
        #pragma unroll
        for (int i = 0; i < 4; i++) {
            const int r = row0 + wm + 16*i + g;
            float2 v0, v1;
            v0.x = acc[i][j][0] + bx; v0.y = acc[i][j][1] + by;
            v1.x = acc[i][j][2] + bx; v1.y = acc[i][j][3] + by;
            if (RELU) {
                v0.x = fmaxf(v0.x, 0.f); v0.y = fmaxf(v0.y, 0.f);
                v1.x = fmaxf(v1.x, 0.f); v1.y = fmaxf(v1.y, 0.f);
            }
            *(float2*)&C[(long)r*ldc + cb]       = v0;
            *(float2*)&C[(long)(r + 8)*ldc + cb] = v1;
        }
    }
}

// ===========================================================================
// Flash attention v3 — validated (round 11).
// ===========================================================================
#define TSF 68
#define PST 66
#define FLASH_SMEM 210944

template<bool CAUSAL>
__global__ __launch_bounds__(256, 1) void flash_k(
    const float* __restrict__ Qg, const float* __restrict__ Kg,
    const float* __restrict__ Vg, float* __restrict__ Yg)
{
    extern __shared__ float sm[];
    constexpr int QHOFF = 0;
    constexpr int QLOFF = 128*TSF;
    constexpr int KOFF  = 2*128*TSF;
    constexpr int VOFF  = 3*128*TSF;
    constexpr int POFF  = 4*128*TSF;
    constexpr int RMOFF = POFF + 128*PST*2;
    constexpr int RSOFF = RMOFF + 512;

    const int qb = blockIdx.x;
    const int bh = blockIdx.y;
    const long base = ((long)(bh >> 3)*SEQ)*DMODEL + (bh & 7)*DHEAD;
    const float* Kp = Kg + base;
    const float* Vp = Vg + base;

    const int tid = threadIdx.x;
    const int wid = tid >> 5, lane = tid & 31;
    const int g = lane >> 2, t = lane & 3;
    const int wy = wid >> 2, wx = wid & 3;

    const int nb = CAUSAL ? (qb + 1) : (SEQ/128);

    auto load_tile = [&](int off, const float* src) {
        #pragma unroll
        for (int it = 0; it < 8; it++) {
            const int idx = tid + (it << 8);
            const int r = idx >> 4, c = (idx & 15) << 2;
            uint32_t d = (uint32_t)__cvta_generic_to_shared(sm + off + r*TSF + c);
            CP_ASYNC16(d, src + (long)r*DMODEL + c);
        }
    };

    load_tile(KOFF, Qg + base + (long)qb*128*DMODEL);
    CP_COMMIT(); CP_WAIT0();
    __syncthreads();
    {
        uint32_t* QH = (uint32_t*)(sm + QHOFF);
        uint32_t* QL = (uint32_t*)(sm + QLOFF);
        const float* qsrc = sm + KOFF;
        #pragma unroll
        for (int i2 = 0; i2 < 32; i2++) {
            const int p = tid + (i2 << 8);
            const int r = p >> 6, c = p & 63;
            uint32_t h, l;
            tf32_split(qsrc[r*TSF + c], h, l);
            QH[r*TSF + c] = h;
            QL[r*TSF + c] = l;
        }
    }
    __syncthreads();

    const uint32_t* QH = (const uint32_t*)(sm + QHOFF);
    const uint32_t* QL = (const uint32_t*)(sm + QLOFF);

    float m[8], l[8];
    #pragma unroll
    for (int s = 0; s < 8; s++) { m[s] = -1e30f; l[s] = 0.f; }
    float accO[4][2][4] = {};

    uint2* Pp = (uint2*)(sm + POFF);

    for (int n = 0; n < nb; n++) {
        __syncthreads();
        load_tile(KOFF, Kp + (long)n*128*DMODEL);
        load_tile(VOFF, Vp + (long)n*128*DMODEL);
        CP_COMMIT(); CP_WAIT0();
        __syncthreads();

        float accS[4][4][4] = {};
        #pragma unroll
        for (int kk = 0; kk < 64; kk += 8) {
            uint32_t ahi[4][4], alo[4][4];
            #pragma unroll
            for (int i = 0; i < 4; i++) {
                const int mb = wy*64 + 16*i + g;
                ahi[i][0] = QH[(mb    )*TSF + kk + t    ];
                ahi[i][1] = QH[(mb + 8)*TSF + kk + t    ];
                ahi[i][2] = QH[(mb    )*TSF + kk + t + 4];
                ahi[i][3] = QH[(mb + 8)*TSF + kk + t + 4];
                alo[i][0] = QL[(mb    )*TSF + kk + t    ];
                alo[i][1] = QL[(mb + 8)*TSF + kk + t    ];
                alo[i][2] = QL[(mb    )*TSF + kk + t + 4];
                alo[i][3] = QL[(mb + 8)*TSF + kk + t + 4];
            }
            #pragma unroll
            for (int j = 0; j < 4; j++) {
                const int n0 = wx*32 + 8*j + g;
                uint32_t bhi[2], blo[2];
                tf32_split(sm[KOFF + n0*TSF + kk + t    ], bhi[0], blo[0]);
                tf32_split(sm[KOFF + n0*TSF + kk + t + 4], bhi[1], blo[1]);
                #pragma unroll
                for (int i = 0; i < 4; i++) {
                    mma8(accS[i][j], ahi[i], bhi);
                    mma8(accS[i][j], ahi[i], blo);
                    mma8(accS[i][j], alo[i], bhi);
                }
            }
        }

        if (CAUSAL && n == qb) {
            #pragma unroll
            for (int i = 0; i < 4; i++) {
                const int r0 = wy*64 + 16*i + g;
                #pragma unroll
                for (int j = 0; j < 4; j++) {
                    const int c0 = wx*32 + 8*j + 2*t;
                    if (c0     > r0    ) accS[i][j][0] = -1e30f;
                    if (c0 + 1 > r0    ) accS[i][j][1] = -1e30f;
                    if (c0     > r0 + 8) accS[i][j][2] = -1e30f;
                    if (c0 + 1 > r0 + 8) accS[i][j][3] = -1e30f;
                }
            }
        }

        #pragma unroll
        for (int i = 0; i < 4; i++) {
            #pragma unroll
            for (int rh = 0; rh < 2; rh++) {
                float pm = -1e30f;
                #pragma unroll
                for (int j = 0; j < 4; j++)
                    pm = fmaxf(pm, fmaxf(accS[i][j][2*rh], accS[i][j][2*rh+1]));
                pm = fmaxf(pm, __shfl_xor_sync(0xffffffffu, pm, 1));
                pm = fmaxf(pm, __shfl_xor_sync(0xffffffffu, pm, 2));
                if (t == 0) sm[RMOFF + (wy*64 + 16*i + g + 8*rh)*4 + wx] = pm;
            }
        }
        __syncthreads();

        #pragma unroll
        for (int i = 0; i < 4; i++) {
            #pragma unroll
            for (int rh = 0; rh < 2; rh++) {
                const int s = 2*i + rh;
                const int row = wy*64 + 16*i + g + 8*rh;
                const float* rm = sm + RMOFF + row*4;
                float bm = fmaxf(fmaxf(rm[0], rm[1]), fmaxf(rm[2], rm[3]));
                float mnew = fmaxf(m[s], bm);
                float alpha = __expf((m[s] - mnew) * 0.125f);
                m[s] = mnew;
                l[s] *= alpha;
                #pragma unroll
                for (int j2 = 0; j2 < 2; j2++) {
                    accO[i][j2][2*rh  ] *= alpha;
                    accO[i][j2][2*rh+1] *= alpha;
                }
                float ps = 0.f;
                #pragma unroll
                for (int j = 0; j < 4; j++) {
                    float e0 = __expf((accS[i][j][2*rh  ] - mnew) * 0.125f);
                    float e1 = __expf((accS[i][j][2*rh+1] - mnew) * 0.125f);
                    ps += e0 + e1;
                    uint32_t hi, lo;
                    bf16_split2(e0, e1, hi, lo);
                    Pp[row*PST + wx*16 + 4*j + t] = make_uint2(hi, lo);
                }
                ps += __shfl_xor_sync(0xffffffffu, ps, 1);
                ps += __shfl_xor_sync(0xffffffffu, ps, 2);
                if (t == 0) sm[RSOFF + row*4 + wx] = ps;
            }
        }
        __syncthreads();

        #pragma unroll
        for (int i = 0; i < 4; i++)
            #pragma unroll
            for (int rh = 0; rh < 2; rh++) {
                const int row = wy*64 + 16*i + g + 8*rh;
                const float* rs = sm + RSOFF + row*4;
                l[2*i + rh] += rs[0] + rs[1] + rs[2] + rs[3];
            }

        #pragma unroll
        for (int kt = 0; kt < 8; kt++) {
            uint32_t pahi[4][4], palo[4][4];
            #pragma unroll
            for (int i = 0; i < 4; i++) {
                #pragma unroll
                for (int rr = 0; rr < 4; rr++) {
                    const int r  = wy*64 + 16*i + g + 8*(rr & 1);
                    const int kp = kt*8 + t + 4*(rr >> 1);
                    uint2 hl = Pp[r*PST + kp];
                    pahi[i][rr] = hl.x; palo[i][rr] = hl.y;
                }
            }
            #pragma unroll
            for (int j2 = 0; j2 < 2; j2++) {
                const int n0 = wx*16 + 8*j2 + g;
                uint32_t vh[2], vl[2];
                #pragma unroll
                for (int rr = 0; rr < 2; rr++) {
                    const int kc = kt*16 + 2*t + 8*rr;
                    bf16_split2(sm[VOFF + kc*TSF + n0], sm[VOFF + (kc+1)*TSF + n0],
                                vh[rr], vl[rr]);
                }
                #pragma unroll
                for (int i = 0; i < 4; i++) {
                    mma16(accO[i][j2], pahi[i], vh);
                    mma16(accO[i][j2], pahi[i], vl);
                    mma16(accO[i][j2], palo[i], vh);
                }
            }
        }
    }

    #pragma unroll
    for (int i = 0; i < 4; i++) {
        #pragma unroll
        for (int rh = 0; rh < 2; rh++) {
            const int row = wy*64 + 16*i + g + 8*rh;
            const float inv = 1.f / l[2*i + rh];
            #pragma unroll
            for (int j2 = 0; j2 < 2; j2++) {
                float2 v;
                v.x = accO[i][j2][2*rh  ] * inv;
                v.y = accO[i][j2][2*rh+1] * inv;
                *(float2*)&Yg[base + (long)(qb*128 + row)*DMODEL + wx*16 + 8*j2 + 2*t] = v;
            }
        }
    }
}

// ===========================================================================
// LayerNorm / pos-add
// ===========================================================================
__global__ void add_ln_k(const float* __restrict__ X, const float* __restrict__ Y,
                         const float* __restrict__ g, const float* __restrict__ b,
                         float* __restrict__ O)
{
    const long row = blockIdx.x;
    const float* x = X + row * DMODEL;
    const float* y = Y + row * DMODEL;
    float* o = O + row * DMODEL;
    const int t = threadIdx.x;
    __shared__ float sm[4];

    float v[4];
    float s = 0.f;
    #pragma unroll
    for (int i = 0; i < 4; i++) {
        int j = t + i*128;
        v[i] = x[j] + y[j];
        s += v[i];
    }
    #pragma unroll
    for (int o2 = 16; o2 > 0; o2 >>= 1) s += __shfl_xor_sync(0xffffffffu, s, o2);
    if ((t & 31) == 0) sm[t >> 5] = s;
    __syncthreads();
    const float mu = (sm[0]+sm[1]+sm[2]+sm[3]) * (1.f/DMODEL);
    __syncthreads();
    float var = 0.f;
    #pragma unroll
    for (int i = 0; i < 4; i++) { float d = v[i]-mu; var += d*d; }
    #pragma unroll
    for (int o2 = 16; o2 > 0; o2 >>= 1) var += __shfl_xor_sync(0xffffffffu, var, o2);
    if ((t & 31) == 0) sm[t >> 5] = var;
    __syncthreads();
    const float rs = rsqrtf((sm[0]+sm[1]+sm[2]+sm[3]) * (1.f/DMODEL) + 1e-5f);
    #pragma unroll
    for (int i = 0; i < 4; i++) {
        int j = t + i*128;
        o[j] = (v[i]-mu)*rs*g[j] + b[j];
    }
}

__global__ void addpos_k(const float* __restrict__ x, const float* __restrict__ pos,
                         float* __restrict__ o)
{
    long idx = (long)blockIdx.x * 256 + threadIdx.x;
    long sd  = idx % ((long)SEQ * DMODEL);
    o[idx] = x[idx] + pos[sd];
}

// ===========================================================================
// Host-side launch helpers
// ===========================================================================
static void dense32(const float* A, const uint32_t* Whi, const uint32_t* Wlo,
                    const float* bias, float* C, int M, int N, int K,
                    long sBb, long sCb, long sbz, int nz)
{
    dim3 grid(N/128, M/128, nz);
    gemm_tf32_k<true><<<grid,256,SMEM_D32>>>(A,Whi,Wlo,bias,C,K, K,K,N, sBb,sCb,sbz);
}
static void dense16(const float* A, const uint32_t* Whi, const uint32_t* Wlo,
                    const float* bias, float* C, int M, int N, int K, int ldw, bool relu)
{
    dim3 grid(N/128, M/128, 1);
    if (relu)
        gemm_bf16_k<true,true ><<<grid,256,SMEM_B16>>>(A,Whi,Wlo,bias,C,K, K,ldw,N);
    else
        gemm_bf16_k<true,false><<<grid,256,SMEM_B16>>>(A,Whi,Wlo,bias,C,K, K,ldw,N);
}

extern "C" void kernel_launch(void* const* d_in, const int* in_sizes, int n_in,
                              void* d_out, int out_size)
{
    const float* kv   = (const float*)d_in[0];
    const float* xin  = (const float*)d_in[1];
    const float* pos  = (const float*)d_in[2];
    const float* sqW  = (const float*)d_in[3];  const float* sqb = (const float*)d_in[4];
    const float* skW  = (const float*)d_in[5];  const float* skb = (const float*)d_in[6];
    const float* svW  = (const float*)d_in[7];  const float* svb = (const float*)d_in[8];
    const float* soW  = (const float*)d_in[9];  const float* sob = (const float*)d_in[10];
    const float* cqW  = (const float*)d_in[11]; const float* cqb = (const float*)d_in[12];
    const float* ckW  = (const float*)d_in[13]; const float* ckb = (const float*)d_in[14];
    const float* cvW  = (const float*)d_in[15]; const float* cvb = (const float*)d_in[16];
    const float* coW  = (const float*)d_in[17]; const float* cob = (const float*)d_in[18];
    const float* f1W  = (const float*)d_in[19]; const float* f1b = (const float*)d_in[20];
    const float* f2W  = (const float*)d_in[21]; const float* f2b = (const float*)d_in[22];
    const float* g1   = (const float*)d_in[23]; const float* b1  = (const float*)d_in[24];
    const float* g2   = (const float*)d_in[25]; const float* b2  = (const float*)d_in[26];
    const float* g3   = (const float*)d_in[27]; const float* b3  = (const float*)d_in[28];
    float* out = (float*)d_out;

    cudaFuncSetAttribute(gemm_tf32_k<true>, cudaFuncAttributeMaxDynamicSharedMemorySize, SMEM_D32);
    cudaFuncSetAttribute(gemm_bf16_k<true,false>, cudaFuncAttributeMaxDynamicSharedMemorySize, SMEM_B16);
    cudaFuncSetAttribute(gemm_bf16_k<true,true >, cudaFuncAttributeMaxDynamicSharedMemorySize, SMEM_B16);
    cudaFuncSetAttribute(flash_k<true >, cudaFuncAttributeMaxDynamicSharedMemorySize, FLASH_SMEM);
    cudaFuncSetAttribute(flash_k<false>, cudaFuncAttributeMaxDynamicSharedMemorySize, FLASH_SMEM);

    float *px,*pqkv,*py,*pt,*pf,*pbias;
    uint32_t *pwthi,*pwtlo,*pwhi,*pwlo;
    cudaGetSymbolAddress((void**)&px, g_x);
    cudaGetSymbolAddress((void**)&pqkv, g_qkv);
    cudaGetSymbolAddress((void**)&py, g_y);
    cudaGetSymbolAddress((void**)&pt, g_t);
    cudaGetSymbolAddress((void**)&pf, g_f);
    cudaGetSymbolAddress((void**)&pwthi, g_wthi);
    cudaGetSymbolAddress((void**)&pwtlo, g_wtlo);
    cudaGetSymbolAddress((void**)&pwhi, g_whi);
    cudaGetSymbolAddress((void**)&pwlo, g_wlo);
    cudaGetSymbolAddress((void**)&pbias, g_bias);

    const long DD = (long)DMODEL*DMODEL;
    const long MD = (long)MROWS*DMODEL;

    float* pq = pqkv;
    float* pk = pqkv + MD;
    float* pv = pqkv + 2*MD;

    // tf32 pre-split fams in g_wthi/g_wtlo: sq@0, sk@12DD, cq@24DD, ck@36DD
    const long SQ = 0, CQ = 24*DD, CK = 36*DD;

    // bf16 pre-split fams in g_whi/g_wlo (uint32 offsets)
    const long WDD = 131072;   // 512*256 per layer
    const long WF  = 524288;
    const long SV = 0, SO = 12*WDD, CV = 24*WDD, CO = 36*WDD;
    const long F1 = 48*WDD, F2 = F1 + 12*WF;

    {
        dim3 blk(32, 8);
        tsplit4t_k<<<dim3(16,16,4*NLAYERS), blk>>>(sqW, skW, cqW, ckW, pwthi, pwtlo);
        tsplit4_k<<<dim3(16,16,4*NLAYERS), blk>>>(svW, soW, cvW, coW, pwhi, pwlo);
        tsplit_k<<<dim3(64,16,NLAYERS), blk>>>(f1W, pwhi + F1, pwlo + F1, DMODEL, FDIM);
        tsplit_k<<<dim3(16,64,NLAYERS), blk>>>(f2W, pwhi + F2, pwlo + F2, FDIM, DMODEL);
        packbias_k<<<(4*NLAYERS*DMODEL)/256, 256>>>(sqb, skb, sqb, sqb, pbias);
    }

    addpos_k<<<(MROWS*DMODEL)/256, 256>>>(xin, pos, px);

    const long LB = (long)NLAYERS*DMODEL;
    const dim3 fgrid(SEQ/128, BATCH*NHEADS);

    for (int l = 0; l < NLAYERS; l++) {
        // ---- self-attention (causal) ----
        dense32(px, pwthi + SQ + l*DD, pwtlo + SQ + l*DD, pbias + l*DMODEL, pq,
                MROWS, DMODEL, DMODEL, 12*DD, MD, LB, 2);      // Q and K batched
        dense16(px, pwhi + SV + l*WDD, pwlo + SV + l*WDD, svb + l*DMODEL, pv,
                MROWS, DMODEL, DMODEL, 256, false);
        flash_k<true ><<<fgrid, 256, FLASH_SMEM>>>(pq, pk, pv, py);
        dense16(py, pwhi + SO + l*WDD, pwlo + SO + l*WDD, sob + l*DMODEL, pt,
                MROWS, DMODEL, DMODEL, 256, false);
        add_ln_k<<<MROWS, 128>>>(px, pt, g1 + l*DMODEL, b1 + l*DMODEL, px);

        // ---- cross-attention ----
        dense32(px, pwthi + CQ + l*DD, pwtlo + CQ + l*DD, cqb + l*DMODEL, pq,
                MROWS, DMODEL, DMODEL, 0, 0, 0, 1);
        dense32(kv, pwthi + CK + l*DD, pwtlo + CK + l*DD, ckb + l*DMODEL, pk,
                MROWS, DMODEL, DMODEL, 0, 0, 0, 1);
        dense16(kv, pwhi + CV + l*WDD, pwlo + CV + l*WDD, cvb + l*DMODEL, pv,
                MROWS, DMODEL, DMODEL, 256, false);
        flash_k<false><<<fgrid, 256, FLASH_SMEM>>>(pq, pk, pv, py);
        dense16(py, pwhi + CO + l*WDD, pwlo + CO + l*WDD, cob + l*DMODEL, pt,
                MROWS, DMODEL, DMODEL, 256, false);
        add_ln_k<<<MROWS, 128>>>(px, pt, g2 + l*DMODEL, b2 + l*DMODEL, px);

        // ---- FFN ----
        dense16(px, pwhi + F1 + l*WF, pwlo + F1 + l*WF, f1b + l*FDIM, pf,
                MROWS, FDIM, DMODEL, 256, true);
        dense16(pf, pwhi + F2 + l*WF, pwlo + F2 + l*WF, f2b + l*DMODEL, pt,
                MROWS, DMODEL, FDIM, 1024, false);
        add_ln_k<<<MROWS, 128>>>(px, pt, g3 + l*DMODEL, b3 + l*DMODEL,
                                 (l == NLAYERS-1) ? out : px);
    }
}

// round 14
// speedup vs baseline: 1.0156x; 1.0156x over previous
#include <cuda_runtime.h>
#include <cstdint>

// Problem constants
#define NLAYERS 12
#define BATCH   4
#define SEQ     1024
#define DMODEL  512
#define NHEADS  8
#define DHEAD   64
#define FDIM    2048
#define MROWS   (BATCH*SEQ)   // 4096

// ===========================================================================
// sm_80-level PTX helpers
// ===========================================================================
#define CP_ASYNC16(dst, src) \
    asm volatile("cp.async.cg.shared.global [%0], [%1], 16;" :: "r"(dst), "l"(src))
#define CP_COMMIT() asm volatile("cp.async.commit_group;" ::: "memory")
#define CP_WAIT0()  asm volatile("cp.async.wait_group 0;" ::: "memory")
#define CP_WAIT1()  asm volatile("cp.async.wait_group 1;" ::: "memory")

__device__ __forceinline__ void tf32_split(float x, uint32_t& hi, uint32_t& lo) {
    uint32_t h;
    asm("cvt.rna.tf32.f32 %0, %1;" : "=r"(h) : "f"(x));
    float r = x - __uint_as_float(h);
    uint32_t l;
    asm("cvt.rna.tf32.f32 %0, %1;" : "=r"(l) : "f"(r));
    hi = h; lo = l;
}

// Split two fp32 (k-adjacent pair) into packed bf16x2 hi and lo parts.
__device__ __forceinline__ void bf16_split2(float x0, float x1,
                                            uint32_t& hi, uint32_t& lo) {
    uint32_t h;
    asm("cvt.rn.bf16x2.f32 %0, %1, %2;" : "=r"(h) : "f"(x1), "f"(x0));
    float h0 = __uint_as_float(h << 16);
    float h1 = __uint_as_float(h & 0xffff0000u);
    float r0 = x0 - h0, r1 = x1 - h1;
    uint32_t l;
    asm("cvt.rn.bf16x2.f32 %0, %1, %2;" : "=r"(l) : "f"(r1), "f"(r0));
    hi = h; lo = l;
}

__device__ __forceinline__ void mma8(float* c, const uint32_t* a, const uint32_t* b) {
    asm volatile(
        "mma.sync.aligned.m16n8k8.row.col.f32.tf32.tf32.f32 "
        "{%0,%1,%2,%3}, {%4,%5,%6,%7}, {%8,%9}, {%0,%1,%2,%3};"
        : "+f"(c[0]), "+f"(c[1]), "+f"(c[2]), "+f"(c[3])
        : "r"(a[0]), "r"(a[1]), "r"(a[2]), "r"(a[3]), "r"(b[0]), "r"(b[1]));
}

__device__ __forceinline__ void mma16(float* c, const uint32_t* a, const uint32_t* b) {
    asm volatile(
        "mma.sync.aligned.m16n8k16.row.col.f32.bf16.bf16.f32 "
        "{%0,%1,%2,%3}, {%4,%5,%6,%7}, {%8,%9}, {%0,%1,%2,%3};"
        : "+f"(c[0]), "+f"(c[1]), "+f"(c[2]), "+f"(c[3])
        : "r"(a[0]), "r"(a[1]), "r"(a[2]), "r"(a[3]), "r"(b[0]), "r"(b[1]));
}

// ===========================================================================
// Scratch (static device globals; no allocation anywhere)
// ===========================================================================
__device__ float g_x[MROWS*DMODEL];
__device__ float g_qkv[3L*MROWS*DMODEL];     // q, k, v slabs
__device__ float g_y[MROWS*DMODEL];
__device__ float g_t[MROWS*DMODEL];
__device__ float g_f[MROWS*FDIM];
__device__ float g_wt[48L*DMODEL*DMODEL];    // tf32 fams transposed fp32: sq sk cq ck
// bf16 pre-split weights, packed bf16x2 along K: [fam][layer][N][K/2]
__device__ uint32_t g_whi[18874368];
__device__ uint32_t g_wlo[18874368];
__device__ float g_bias[4L*NLAYERS*DMODEL];  // packed biases (slots 0,1: sq, sk)

// ===========================================================================
// Setup kernels
// ===========================================================================
// Transpose 4 DxD tf32-path families in one launch (z = 4*12) -> fp32 [N][K]
__global__ void transpose4_k(const float* __restrict__ s0, const float* __restrict__ s1,
                             const float* __restrict__ s2, const float* __restrict__ s3,
                             float* __restrict__ dstBase)
{
    __shared__ float tt[32][33];
    const int z = blockIdx.z;
    const int f = z / NLAYERS, ly = z % NLAYERS;
    const float* S = (f == 0) ? s0 : (f == 1) ? s1 : (f == 2) ? s2 : s3;
    const long DD = (long)DMODEL*DMODEL;
    S += (long)ly * DD;
    float* D = dstBase + (long)f*NLAYERS*DD + (long)ly*DD;

    const int c0 = blockIdx.x * 32, r0 = blockIdx.y * 32;
    const int tx = threadIdx.x, ty = threadIdx.y;
    #pragma unroll
    for (int i = 0; i < 32; i += 8)
        tt[ty + i][tx] = S[(long)(r0 + ty + i)*DMODEL + c0 + tx];
    __syncthreads();
    #pragma unroll
    for (int i = 0; i < 32; i += 8)
        D[(long)(c0 + ty + i)*DMODEL + r0 + tx] = tt[tx][ty + i];
}

// Transpose + bf16-split 4 DxD bf16-path families (z = 4*12).
__global__ void tsplit4_k(const float* __restrict__ s0, const float* __restrict__ s1,
                          const float* __restrict__ s2, const float* __restrict__ s3,
                          uint32_t* __restrict__ dhi, uint32_t* __restrict__ dlo)
{
    __shared__ float tt[32][33];
    const int z = blockIdx.z;
    const int f = z / NLAYERS, ly = z % NLAYERS;
    const float* S = (f == 0) ? s0 : (f == 1) ? s1 : (f == 2) ? s2 : s3;
    S += (long)ly * DMODEL*DMODEL;
    const long obase = (long)f*NLAYERS*DMODEL*(DMODEL/2) + (long)ly*DMODEL*(DMODEL/2);
    uint32_t* DH = dhi + obase;
    uint32_t* DL = dlo + obase;

    const int k0 = blockIdx.y * 32, n0 = blockIdx.x * 32;
    const int tx = threadIdx.x, ty = threadIdx.y;
    #pragma unroll
    for (int i = 0; i < 32; i += 8)
        tt[ty + i][tx] = S[(long)(k0 + ty + i)*DMODEL + n0 + tx];
    __syncthreads();
    const int base = ty*32 + tx;
    #pragma unroll
    for (int q = 0; q < 2; q++) {
        const int o = base + q*256;
        const int nl = o >> 4, kkl = o & 15;
        uint32_t h, l;
        bf16_split2(tt[2*kkl][nl], tt[2*kkl + 1][nl], h, l);
        DH[(long)(n0 + nl)*(DMODEL/2) + (k0 >> 1) + kkl] = h;
        DL[(long)(n0 + nl)*(DMODEL/2) + (k0 >> 1) + kkl] = l;
    }
}

// Generic transpose+bf16-split (f1: R=512,C=2048; f2: R=2048,C=512)
__global__ void tsplit_k(const float* __restrict__ S, uint32_t* __restrict__ DH,
                         uint32_t* __restrict__ DL, int R, int C)
{
    __shared__ float tt[32][33];
    const long ly = blockIdx.z;
    S  += ly * (long)R * C;
    DH += ly * (long)C * (R/2);
    DL += ly * (long)C * (R/2);

    const int k0 = blockIdx.y * 32, n0 = blockIdx.x * 32;
    const int tx = threadIdx.x, ty = threadIdx.y;
    #pragma unroll
    for (int i = 0; i < 32; i += 8)
        tt[ty + i][tx] = S[(long)(k0 + ty + i)*C + n0 + tx];
    __syncthreads();
    const int base = ty*32 + tx;
    #pragma unroll
    for (int q = 0; q < 2; q++) {
        const int o = base + q*256;
        const int nl = o >> 4, kkl = o & 15;
        uint32_t h, l;
        bf16_split2(tt[2*kkl][nl], tt[2*kkl + 1][nl], h, l);
        DH[(long)(n0 + nl)*(R/2) + (k0 >> 1) + kkl] = h;
        DL[(long)(n0 + nl)*(R/2) + (k0 >> 1) + kkl] = l;
    }
}

__global__ void packbias_k(const float* __restrict__ a0, const float* __restrict__ a1,
                           const float* __restrict__ a2, const float* __restrict__ a3,
                           float* __restrict__ dst)
{
    const int i = blockIdx.x*256 + threadIdx.x;
    const int f = i / (NLAYERS*DMODEL), r = i % (NLAYERS*DMODEL);
    const float* s = (f == 0) ? a0 : (f == 1) ? a1 : (f == 2) ? a2 : a3;
    dst[i] = s[r];
}

// ===========================================================================
// tf32 GEMM v3 — B fp32 (TB, transposed weights) with in-loop split
// (round-11 validated), PLUS A-split staged in SMEM (traffic-neutral).
// SMEM floats: A 2x2560 | AH 2560 | AL 2560 | B 2x2560 = 15360 fl = 61440 B
// ===========================================================================
#define SMEM_D32 61440

template<bool BIAS>
__global__ __launch_bounds__(256, 1) void gemm_tf32_k(
    const float* __restrict__ A, const float* __restrict__ Bm,
    const float* __restrict__ bias, float* __restrict__ C,
    int K, int lda, int ldb, int ldc,
    long sBb, long sCb, long sbz)
{
    constexpr int AS = 20;
    constexpr int BS = 20;

    const int row0 = blockIdx.y * 128;
    const int col0 = blockIdx.x * 128;
    const int zb = blockIdx.z;
    Bm += (long)zb*sBb;
    C  += (long)zb*sCb;
    if (BIAS) bias += (long)zb*sbz;

    extern __shared__ float smf[];
    float*    Asm = smf;                          // 2 x 2560
    uint32_t* AH  = (uint32_t*)(smf + 5120);      // 2560
    uint32_t* AL  = (uint32_t*)(smf + 7680);      // 2560
    float*    Bsm = smf + 10240;                  // 2 x 2560

    const int tid  = threadIdx.x;
    const int wid  = tid >> 5;
    const int lane = tid & 31;
    const int g = lane >> 2, t = lane & 3;
    const int wm = (wid >> 2) * 64;
    const int wn = (wid & 3) * 32;

    const int ns = K >> 4;

    auto loadA = [&](int s) {
        float* dst = Asm + (s & 1) * 2560;
        const int r  = tid >> 1;
        const int kc = (tid & 1) << 3;
        uint32_t d = (uint32_t)__cvta_generic_to_shared(dst + r*AS + kc);
        CP_ASYNC16(d, A + (long)(row0 + r)*lda + (s << 4) + kc);
        uint32_t d2 = (uint32_t)__cvta_generic_to_shared(dst + r*AS + kc + 4);
        CP_ASYNC16(d2, A + (long)(row0 + r)*lda + (s << 4) + kc + 4);
    };
    auto loadB = [&](int s) {
        float* dst = Bsm + (s & 1) * 2560;
        const int r  = tid >> 1;
        const int kc = (tid & 1) << 3;
        uint32_t d = (uint32_t)__cvta_generic_to_shared(dst + r*BS + kc);
        CP_ASYNC16(d, Bm + (long)(col0 + r)*ldb + (s << 4) + kc);
        uint32_t d2 = (uint32_t)__cvta_generic_to_shared(dst + r*BS + kc + 4);
        CP_ASYNC16(d2, Bm + (long)(col0 + r)*ldb + (s << 4) + kc + 4);
    };

    float acc[4][4][4] = {};

    loadA(0); loadB(0); CP_COMMIT();

    for (int s = 0; s < ns; s++) {
        if (s + 1 < ns) { loadA(s+1); loadB(s+1); CP_COMMIT(); CP_WAIT1(); }
        else            { CP_WAIT0(); }
        __syncthreads();

        // --- stage A tf32-split: 128x16 fp32 -> AH/AL [128][16] (stride 20) ---
        {
            const float* a = Asm + (s & 1) * 2560;
            #pragma unroll
            for (int p2 = 0; p2 < 8; p2++) {
                const int p = tid + (p2 << 8);
                const int r = p >> 4, c = p & 15;
                uint32_t h, l;
                tf32_split(a[r*AS + c], h, l);
                AH[r*AS + c] = h;
                AL[r*AS + c] = l;
            }
        }
        __syncthreads();

        const float* b = Bsm + (s & 1) * 2560;

        #pragma unroll
        for (int kk = 0; kk < 16; kk += 8) {
            uint32_t ahi[4][4], alo[4][4];
            #pragma unroll
            for (int i = 0; i < 4; i++) {
                const int m0 = wm + 16*i + g;
                ahi[i][0] = AH[(m0    )*AS + kk + t    ];
                ahi[i][1] = AH[(m0 + 8)*AS + kk + t    ];
                ahi[i][2] = AH[(m0    )*AS + kk + t + 4];
                ahi[i][3] = AH[(m0 + 8)*AS + kk + t + 4];
                alo[i][0] = AL[(m0    )*AS + kk + t    ];
                alo[i][1] = AL[(m0 + 8)*AS + kk + t    ];
                alo[i][2] = AL[(m0    )*AS + kk + t + 4];
                alo[i][3] = AL[(m0 + 8)*AS + kk + t + 4];
            }
            #pragma unroll
            for (int j = 0; j < 4; j++) {
                const int n0 = wn + 8*j + g;
                uint32_t bhi[2], blo[2];
                tf32_split(b[n0*BS + kk + t    ], bhi[0], blo[0]);
                tf32_split(b[n0*BS + kk + t + 4], bhi[1], blo[1]);
                #pragma unroll
                for (int i = 0; i < 4; i++) {
                    mma8(acc[i][j], ahi[i], bhi);
                    mma8(acc[i][j], ahi[i], blo);
                    mma8(acc[i][j], alo[i], bhi);
                }
            }
        }
        __syncthreads();
    }

    #pragma unroll
    for (int j = 0; j < 4; j++) {
        const int cb = col0 + wn + 8*j + 2*t;
        float bx = 0.f, by = 0.f;
        if (BIAS) { bx = bias[cb]; by = bias[cb + 1]; }
        #pragma unroll
        for (int i = 0; i < 4; i++) {
            const int r = row0 + wm + 16*i + g;
            float2 v0, v1;
            v0.x = acc[i][j][0] + bx; v0.y = acc[i][j][1] + by;
            v1.x = acc[i][j][2] + bx; v1.y = acc[i][j][3] + by;
            *(float2*)&C[(long)r*ldc + cb]       = v0;
            *(float2*)&C[(long)(r + 8)*ldc + cb] = v1;
        }
    }
}

// ===========================================================================
// bf16 GEMM v2 — validated (round 11), unchanged.
// ===========================================================================
#define SMEM_B16 57344

template<bool BIAS, bool RELU>
__global__ __launch_bounds__(256, 1) void gemm_bf16_k(
    const float* __restrict__ A, const uint32_t* __restrict__ Whi,
    const uint32_t* __restrict__ Wlo, const float* __restrict__ bias,
    float* __restrict__ C, int K, int lda, int ldw, int ldc)
{
    constexpr int AS = 20;
    constexpr int WS = 12;

    const int row0 = blockIdx.y * 128;
    const int col0 = blockIdx.x * 128;

    extern __shared__ float smf[];
    float*    Asm = smf;                          // 2 * 2560
    uint32_t* AH  = (uint32_t*)(smf + 5120);      // 1536
    uint32_t* AL  = (uint32_t*)(smf + 6656);      // 1536
    uint32_t* BH  = (uint32_t*)(smf + 8192);      // 2 * 1536
    uint32_t* BL  = (uint32_t*)(smf + 11264);     // 2 * 1536

    const int tid  = threadIdx.x;
    const int wid  = tid >> 5;
    const int lane = tid & 31;
    const int g = lane >> 2, t = lane & 3;
    const int wm = (wid >> 2) * 64;
    const int wn = (wid & 3) * 32;

    const int ns = K >> 4;

    auto loadA = [&](int s) {
        float* dst = Asm + (s & 1) * 2560;
        const int r  = tid >> 1;
        const int kc = (tid & 1) << 3;
        uint32_t d = (uint32_t)__cvta_generic_to_shared(dst + r*AS + kc);
        CP_ASYNC16(d, A + (long)(row0 + r)*lda + (s << 4) + kc);
        uint32_t d2 = (uint32_t)__cvta_generic_to_shared(dst + r*AS + kc + 4);
        CP_ASYNC16(d2, A + (long)(row0 + r)*lda + (s << 4) + kc + 4);
    };
    auto loadB = [&](int s) {
        uint32_t* dh = BH + (s & 1) * 1536;
        uint32_t* dl = BL + (s & 1) * 1536;
        const int r = tid >> 1, half = (tid & 1) << 2;
        uint32_t d = (uint32_t)__cvta_generic_to_shared(dh + r*WS + half);
        CP_ASYNC16(d, Whi + (long)(col0 + r)*ldw + (s << 3) + half);
        uint32_t d2 = (uint32_t)__cvta_generic_to_shared(dl + r*WS + half);
        CP_ASYNC16(d2, Wlo + (long)(col0 + r)*ldw + (s << 3) + half);
    };

    float acc[4][4][4] = {};

    loadA(0); loadB(0); CP_COMMIT();

    for (int s = 0; s < ns; s++) {
        if (s + 1 < ns) { loadA(s+1); loadB(s+1); CP_COMMIT(); CP_WAIT1(); }
        else            { CP_WAIT0(); }
        __syncthreads();

        {
            const float* a = Asm + (s & 1) * 2560;
            #pragma unroll
            for (int p2 = 0; p2 < 4; p2++) {
                const int p = tid + (p2 << 8);
                const int r = p >> 3, c2 = p & 7;
                float2 x = *(const float2*)&a[r*AS + 2*c2];
                uint32_t h, l;
                bf16_split2(x.x, x.y, h, l);
                AH[r*WS + c2] = h;
                AL[r*WS + c2] = l;
            }
        }
        __syncthreads();

        const uint32_t* bh = BH + (s & 1) * 1536;
        const uint32_t* bl = BL + (s & 1) * 1536;

        uint32_t ahi[4][4], alo[4][4];
        #pragma unroll
        for (int i = 0; i < 4; i++) {
            #pragma unroll
            for (int rr = 0; rr < 4; rr++) {
                const int r  = wm + 16*i + g + 8*(rr & 1);
                const int cc = t + 4*(rr >> 1);
                ahi[i][rr] = AH[r*WS + cc];
                alo[i][rr] = AL[r*WS + cc];
            }
        }
        #pragma unroll
        for (int j = 0; j < 4; j++) {
            const int n0 = wn + 8*j + g;
            uint32_t bhi[2], blo[2];
            bhi[0] = bh[n0*WS + t];     bhi[1] = bh[n0*WS + t + 4];
            blo[0] = bl[n0*WS + t];     blo[1] = bl[n0*WS + t + 4];
            #pragma unroll
            for (int i = 0; i < 4; i++) {
                mma16(acc[i][j], ahi[i], bhi);
                mma16(acc[i][j], ahi[i], blo);
                mma16(acc[i][j], alo[i], bhi);
            }
        }
        __syncthreads();
    }

    #pragma unroll
    for (int j = 0; j < 4; j++) {
        const int cb = col0 + wn + 8*j + 2*t;
        float bx = 0.f, by = 0.f;
        if (BIAS) { bx = bias[cb]; by = bias[cb + 1]; }
        #pragma unroll
        for (int i = 0; i < 4; i++) {
            const int r = row0 + wm + 16*i + g;
            float2 v0, v1;
            v0.x = acc[i][j][0] + bx; v0.y = acc[i][j][1] + by;
            v1.x = acc[i][j][2] + bx; v1.y = acc[i][j][3] + by;
            if (RELU) {
                v0.x = fmaxf(v0.x, 0.f); v0.y = fmaxf(v0.y, 0.f);
                v1.x = fmaxf(v1.x, 0.f); v1.y = fmaxf(v1.y, 0.f);
            }
            *(float2*)&C[(long)r*ldc + cb]       = v0;
            *(float2*)&C[(long)(r + 8)*ldc + cb] = v1;
        }
    }
}

// ===========================================================================
// Flash attention v3 — validated (round 11), unchanged.
// ===========================================================================
#define TSF 68
#define PST 66
#define FLASH_SMEM 210944

template<bool CAUSAL>
__global__ __launch_bounds__(256, 1) void flash_k(
    const float* __restrict__ Qg, const float* __restrict__ Kg,
    const float* __restrict__ Vg, float* __restrict__ Yg)
{
    extern __shared__ float sm[];
    constexpr int QHOFF = 0;
    constexpr int QLOFF = 128*TSF;
    constexpr int KOFF  = 2*128*TSF;
    constexpr int VOFF  = 3*128*TSF;
    constexpr int POFF  = 4*128*TSF;
    constexpr int RMOFF = POFF + 128*PST*2;
    constexpr int RSOFF = RMOFF + 512;

    const int qb = blockIdx.x;
    const int bh = blockIdx.y;
    const long base = ((long)(bh >> 3)*SEQ)*DMODEL + (bh & 7)*DHEAD;
    const float* Kp = Kg + base;
    const float* Vp = Vg + base;

    const int tid = threadIdx.x;
    const int wid = tid >> 5, lane = tid & 31;
    const int g = lane >> 2, t = lane & 3;
    const int wy = wid >> 2, wx = wid & 3;

    const int nb = CAUSAL ? (qb + 1) : (SEQ/128);

    auto load_tile = [&](int off, const float* src) {
        #pragma unroll
        for (int it = 0; it < 8; it++) {
            const int idx = tid + (it << 8);
            const int r = idx >> 4, c = (idx & 15) << 2;
            uint32_t d = (uint32_t)__cvta_generic_to_shared(sm + off + r*TSF + c);
            CP_ASYNC16(d, src + (long)r*DMODEL + c);
        }
    };

    load_tile(KOFF, Qg + base + (long)qb*128*DMODEL);
    CP_COMMIT(); CP_WAIT0();
    __syncthreads();
    {
        uint32_t* QH = (uint32_t*)(sm + QHOFF);
        uint32_t* QL = (uint32_t*)(sm + QLOFF);
        const float* qsrc = sm + KOFF;
        #pragma unroll
        for (int i2 = 0; i2 < 32; i2++) {
            const int p = tid + (i2 << 8);
            const int r = p >> 6, c = p & 63;
            uint32_t h, l;
            tf32_split(qsrc[r*TSF + c], h, l);
            QH[r*TSF + c] = h;
            QL[r*TSF + c] = l;
        }
    }
    __syncthreads();

    const uint32_t* QH = (const uint32_t*)(sm + QHOFF);
    const uint32_t* QL = (const uint32_t*)(sm + QLOFF);

    float m[8], l[8];
    #pragma unroll
    for (int s = 0; s < 8; s++) { m[s] = -1e30f; l[s] = 0.f; }
    float accO[4][2][4] = {};

    uint2* Pp = (uint2*)(sm + POFF);

    for (int n = 0; n < nb; n++) {
        __syncthreads();
        load_tile(KOFF, Kp + (long)n*128*DMODEL);
        load_tile(VOFF, Vp + (long)n*128*DMODEL);
        CP_COMMIT(); CP_WAIT0();
        __syncthreads();

        float accS[4][4][4] = {};
        #pragma unroll
        for (int kk = 0; kk < 64; kk += 8) {
            uint32_t ahi[4][4], alo[4][4];
            #pragma unroll
            for (int i = 0; i < 4; i++) {
                const int mb = wy*64 + 16*i + g;
                ahi[i][0] = QH[(mb    )*TSF + kk + t    ];
                ahi[i][1] = QH[(mb + 8)*TSF + kk + t    ];
                ahi[i][2] = QH[(mb    )*TSF + kk + t + 4];
                ahi[i][3] = QH[(mb + 8)*TSF + kk + t + 4];
                alo[i][0] = QL[(mb    )*TSF + kk + t    ];
                alo[i][1] = QL[(mb + 8)*TSF + kk + t    ];
                alo[i][2] = QL[(mb    )*TSF + kk + t + 4];
                alo[i][3] = QL[(mb + 8)*TSF + kk + t + 4];
            }
            #pragma unroll
            for (int j = 0; j < 4; j++) {
                const int n0 = wx*32 + 8*j + g;
                uint32_t bhi[2], blo[2];
                tf32_split(sm[KOFF + n0*TSF + kk + t    ], bhi[0], blo[0]);
                tf32_split(sm[KOFF + n0*TSF + kk + t + 4], bhi[1], blo[1]);
                #pragma unroll
                for (int i = 0; i < 4; i++) {
                    mma8(accS[i][j], ahi[i], bhi);
                    mma8(accS[i][j], ahi[i], blo);
                    mma8(accS[i][j], alo[i], bhi);
                }
            }
        }

        if (CAUSAL && n == qb) {
            #pragma unroll
            for (int i = 0; i < 4; i++) {
                const int r0 = wy*64 + 16*i + g;
                #pragma unroll
                for (int j = 0; j < 4; j++) {
                    const int c0 = wx*32 + 8*j + 2*t;
                    if (c0     > r0    ) accS[i][j][0] = -1e30f;
                    if (c0 + 1 > r0    ) accS[i][j][1] = -1e30f;
                    if (c0     > r0 + 8) accS[i][j][2] = -1e30f;
                    if (c0 + 1 > r0 + 8) accS[i][j][3] = -1e30f;
                }
            }
        }

        #pragma unroll
        for (int i = 0; i < 4; i++) {
            #pragma unroll
            for (int rh = 0; rh < 2; rh++) {
                float pm = -1e30f;
                #pragma unroll
                for (int j = 0; j < 4; j++)
                    pm = fmaxf(pm, fmaxf(accS[i][j][2*rh], accS[i][j][2*rh+1]));
                pm = fmaxf(pm, __shfl_xor_sync(0xffffffffu, pm, 1));
                pm = fmaxf(pm, __shfl_xor_sync(0xffffffffu, pm, 2));
                if (t == 0) sm[RMOFF + (wy*64 + 16*i + g + 8*rh)*4 + wx] = pm;
            }
        }
        __syncthreads();

        #pragma unroll
        for (int i = 0; i < 4; i++) {
            #pragma unroll
            for (int rh = 0; rh < 2; rh++) {
                const int s = 2*i + rh;
                const int row = wy*64 + 16*i + g + 8*rh;
                const float* rm = sm + RMOFF + row*4;
                float bm = fmaxf(fmaxf(rm[0], rm[1]), fmaxf(rm[2], rm[3]));
                float mnew = fmaxf(m[s], bm);
                float alpha = __expf((m[s] - mnew) * 0.125f);
                m[s] = mnew;
                l[s] *= alpha;
                #pragma unroll
                for (int j2 = 0; j2 < 2; j2++) {
                    accO[i][j2][2*rh  ] *= alpha;
                    accO[i][j2][2*rh+1] *= alpha;
                }
                float ps = 0.f;
                #pragma unroll
                for (int j = 0; j < 4; j++) {
                    float e0 = __expf((accS[i][j][2*rh  ] - mnew) * 0.125f);
                    float e1 = __expf((accS[i][j][2*rh+1] - mnew) * 0.125f);
                    ps += e0 + e1;
                    uint32_t hi, lo;
                    bf16_split2(e0, e1, hi, lo);
                    Pp[row*PST + wx*16 + 4*j + t] = make_uint2(hi, lo);
                }
                ps += __shfl_xor_sync(0xffffffffu, ps, 1);
                ps += __shfl_xor_sync(0xffffffffu, ps, 2);
                if (t == 0) sm[RSOFF + row*4 + wx] = ps;
            }
        }
        __syncthreads();

        #pragma unroll
        for (int i = 0; i < 4; i++)
            #pragma unroll
            for (int rh = 0; rh < 2; rh++) {
                const int row = wy*64 + 16*i + g + 8*rh;
                const float* rs = sm + RSOFF + row*4;
                l[2*i + rh] += rs[0] + rs[1] + rs[2] + rs[3];
            }

        #pragma unroll
        for (int kt = 0; kt < 8; kt++) {
            uint32_t pahi[4][4], palo[4][4];
            #pragma unroll
            for (int i = 0; i < 4; i++) {
                #pragma unroll
                for (int rr = 0; rr < 4; rr++) {
                    const int r  = wy*64 + 16*i + g + 8*(rr & 1);
                    const int kp = kt*8 + t + 4*(rr >> 1);
                    uint2 hl = Pp[r*PST + kp];
                    pahi[i][rr] = hl.x; palo[i][rr] = hl.y;
                }
            }
            #pragma unroll
            for (int j2 = 0; j2 < 2; j2++) {
                const int n0 = wx*16 + 8*j2 + g;
                uint32_t vh[2], vl[2];
                #pragma unroll
                for (int rr = 0; rr < 2; rr++) {
                    const int kc = kt*16 + 2*t + 8*rr;
                    bf16_split2(sm[VOFF + kc*TSF + n0], sm[VOFF + (kc+1)*TSF + n0],
                                vh[rr], vl[rr]);
                }
                #pragma unroll
                for (int i = 0; i < 4; i++) {
                    mma16(accO[i][j2], pahi[i], vh);
                    mma16(accO[i][j2], pahi[i], vl);
                    mma16(accO[i][j2], palo[i], vh);
                }
            }
        }
    }

    #pragma unroll
    for (int i = 0; i < 4; i++) {
        #pragma unroll
        for (int rh = 0; rh < 2; rh++) {
            const int row = wy*64 + 16*i + g + 8*rh;
            const float inv = 1.f / l[2*i + rh];
            #pragma unroll
            for (int j2 = 0; j2 < 2; j2++) {
                float2 v;
                v.x = accO[i][j2][2*rh  ] * inv;
                v.y = accO[i][j2][2*rh+1] * inv;
                *(float2*)&Yg[base + (long)(qb*128 + row)*DMODEL + wx*16 + 8*j2 + 2*t] = v;
            }
        }
    }
}

// ===========================================================================
// LayerNorm / pos-add
// ===========================================================================
__global__ void add_ln_k(const float* __restrict__ X, const float* __restrict__ Y,
                         const float* __restrict__ g, const float* __restrict__ b,
                         float* __restrict__ O)
{
    const long row = blockIdx.x;
    const float* x = X + row * DMODEL;
    const float* y = Y + row * DMODEL;
    float* o = O + row * DMODEL;
    const int t = threadIdx.x;
    __shared__ float sm[4];

    float v[4];
    float s = 0.f;
    #pragma unroll
    for (int i = 0; i < 4; i++) {
        int j = t + i*128;
        v[i] = x[j] + y[j];
        s += v[i];
    }
    #pragma unroll
    for (int o2 = 16; o2 > 0; o2 >>= 1) s += __shfl_xor_sync(0xffffffffu, s, o2);
    if ((t & 31) == 0) sm[t >> 5] = s;
    __syncthreads();
    const float mu = (sm[0]+sm[1]+sm[2]+sm[3]) * (1.f/DMODEL);
    __syncthreads();
    float var = 0.f;
    #pragma unroll
    for (int i = 0; i < 4; i++) { float d = v[i]-mu; var += d*d; }
    #pragma unroll
    for (int o2 = 16; o2 > 0; o2 >>= 1) var += __shfl_xor_sync(0xffffffffu, var, o2);
    if ((t & 31) == 0) sm[t >> 5] = var;
    __syncthreads();
    const float rs = rsqrtf((sm[0]+sm[1]+sm[2]+sm[3]) * (1.f/DMODEL) + 1e-5f);
    #pragma unroll
    for (int i = 0; i < 4; i++) {
        int j = t + i*128;
        o[j] = (v[i]-mu)*rs*g[j] + b[j];
    }
}

__global__ void addpos_k(const float* __restrict__ x, const float* __restrict__ pos,
                         float* __restrict__ o)
{
    long idx = (long)blockIdx.x * 256 + threadIdx.x;
    long sd  = idx % ((long)SEQ * DMODEL);
    o[idx] = x[idx] + pos[sd];
}

// ===========================================================================
// Host-side launch helpers
// ===========================================================================
static void dense32(const float* A, const float* Bt, const float* bias, float* C,
                    int M, int N, int K, long sBb, long sCb, long sbz, int nz)
{
    dim3 grid(N/128, M/128, nz);
    gemm_tf32_k<true><<<grid,256,SMEM_D32>>>(A,Bt,bias,C,K, K,K,N, sBb,sCb,sbz);
}
static void dense16(const float* A, const uint32_t* Whi, const uint32_t* Wlo,
                    const float* bias, float* C, int M, int N, int K, int ldw, bool relu)
{
    dim3 grid(N/128, M/128, 1);
    if (relu)
        gemm_bf16_k<true,true ><<<grid,256,SMEM_B16>>>(A,Whi,Wlo,bias,C,K, K,ldw,N);
    else
        gemm_bf16_k<true,false><<<grid,256,SMEM_B16>>>(A,Whi,Wlo,bias,C,K, K,ldw,N);
}

extern "C" void kernel_launch(void* const* d_in, const int* in_sizes, int n_in,
                              void* d_out, int out_size)
{
    const float* kv   = (const float*)d_in[0];
    const float* xin  = (const float*)d_in[1];
    const float* pos  = (const float*)d_in[2];
    const float* sqW  = (const float*)d_in[3];  const float* sqb = (const float*)d_in[4];
    const float* skW  = (const float*)d_in[5];  const float* skb = (const float*)d_in[6];
    const float* svW  = (const float*)d_in[7];  const float* svb = (const float*)d_in[8];
    const float* soW  = (const float*)d_in[9];  const float* sob = (const float*)d_in[10];
    const float* cqW  = (const float*)d_in[11]; const float* cqb = (const float*)d_in[12];
    const float* ckW  = (const float*)d_in[13]; const float* ckb = (const float*)d_in[14];
    const float* cvW  = (const float*)d_in[15]; const float* cvb = (const float*)d_in[16];
    const float* coW  = (const float*)d_in[17]; const float* cob = (const float*)d_in[18];
    const float* f1W  = (const float*)d_in[19]; const float* f1b = (const float*)d_in[20];
    const float* f2W  = (const float*)d_in[21]; const float* f2b = (const float*)d_in[22];
    const float* g1   = (const float*)d_in[23]; const float* b1  = (const float*)d_in[24];
    const float* g2   = (const float*)d_in[25]; const float* b2  = (const float*)d_in[26];
    const float* g3   = (const float*)d_in[27]; const float* b3  = (const float*)d_in[28];
    float* out = (float*)d_out;

    cudaFuncSetAttribute(gemm_tf32_k<true>, cudaFuncAttributeMaxDynamicSharedMemorySize, SMEM_D32);
    cudaFuncSetAttribute(gemm_bf16_k<true,false>, cudaFuncAttributeMaxDynamicSharedMemorySize, SMEM_B16);
    cudaFuncSetAttribute(gemm_bf16_k<true,true >, cudaFuncAttributeMaxDynamicSharedMemorySize, SMEM_B16);
    cudaFuncSetAttribute(flash_k<true >, cudaFuncAttributeMaxDynamicSharedMemorySize, FLASH_SMEM);
    cudaFuncSetAttribute(flash_k<false>, cudaFuncAttributeMaxDynamicSharedMemorySize, FLASH_SMEM);

    float *px,*pqkv,*py,*pt,*pf,*pwt,*pbias;
    uint32_t *pwhi,*pwlo;
    cudaGetSymbolAddress((void**)&px, g_x);
    cudaGetSymbolAddress((void**)&pqkv, g_qkv);
    cudaGetSymbolAddress((void**)&py, g_y);
    cudaGetSymbolAddress((void**)&pt, g_t);
    cudaGetSymbolAddress((void**)&pf, g_f);
    cudaGetSymbolAddress((void**)&pwt, g_wt);
    cudaGetSymbolAddress((void**)&pwhi, g_whi);
    cudaGetSymbolAddress((void**)&pwlo, g_wlo);
    cudaGetSymbolAddress((void**)&pbias, g_bias);

    const long DD = (long)DMODEL*DMODEL;
    const long MD = (long)MROWS*DMODEL;

    float* pq = pqkv;
    float* pk = pqkv + MD;
    float* pv = pqkv + 2*MD;

    // tf32 transposed fams in g_wt: sq@0, sk@12DD, cq@24DD, ck@36DD
    float* sqT = pwt;
    float* cqT = pwt + 24*DD;
    float* ckT = pwt + 36*DD;

    // bf16 pre-split fams in g_whi/g_wlo (uint32 offsets)
    const long WDD = 131072;   // 512*256 per layer
    const long WF  = 524288;
    const long SV = 0, SO = 12*WDD, CV = 24*WDD, CO = 36*WDD;
    const long F1 = 48*WDD, F2 = F1 + 12*WF;

    {
        dim3 blk(32, 8);
        transpose4_k<<<dim3(16,16,4*NLAYERS), blk>>>(sqW, skW, cqW, ckW, pwt);
        tsplit4_k<<<dim3(16,16,4*NLAYERS), blk>>>(svW, soW, cvW, coW, pwhi, pwlo);
        tsplit_k<<<dim3(64,16,NLAYERS), blk>>>(f1W, pwhi + F1, pwlo + F1, DMODEL, FDIM);
        tsplit_k<<<dim3(16,64,NLAYERS), blk>>>(f2W, pwhi + F2, pwlo + F2, FDIM, DMODEL);
        packbias_k<<<(4*NLAYERS*DMODEL)/256, 256>>>(sqb, skb, sqb, sqb, pbias);
    }

    addpos_k<<<(MROWS*DMODEL)/256, 256>>>(xin, pos, px);

    const long LB = (long)NLAYERS*DMODEL;
    const dim3 fgrid(SEQ/128, BATCH*NHEADS);

    for (int l = 0; l < NLAYERS; l++) {
        // ---- self-attention (causal) ----
        dense32(px, sqT + l*DD, pbias + l*DMODEL, pq,
                MROWS, DMODEL, DMODEL, 12*DD, MD, LB, 2);      // Q and K batched
        dense16(px, pwhi + SV + l*WDD, pwlo + SV + l*WDD, svb + l*DMODEL, pv,
                MROWS, DMODEL, DMODEL, 256, false);
        flash_k<true ><<<fgrid, 256, FLASH_SMEM>>>(pq, pk, pv, py);
        dense16(py, pwhi + SO + l*WDD, pwlo + SO + l*WDD, sob + l*DMODEL, pt,
                MROWS, DMODEL, DMODEL, 256, false);
        add_ln_k<<<MROWS, 128>>>(px, pt, g1 + l*DMODEL, b1 + l*DMODEL, px);

        // ---- cross-attention ----
        dense32(px, cqT + l*DD, cqb + l*DMODEL, pq, MROWS, DMODEL, DMODEL, 0, 0, 0, 1);
        dense32(kv, ckT + l*DD, ckb + l*DMODEL, pk, MROWS, DMODEL, DMODEL, 0, 0, 0, 1);
        dense16(kv, pwhi + CV + l*WDD, pwlo + CV + l*WDD, cvb + l*DMODEL, pv,
                MROWS, DMODEL, DMODEL, 256, false);
        flash_k<false><<<fgrid, 256, FLASH_SMEM>>>(pq, pk, pv, py);
        dense16(py, pwhi + CO + l*WDD, pwlo + CO + l*WDD, cob + l*DMODEL, pt,
                MROWS, DMODEL, DMODEL, 256, false);
        add_ln_k<<<MROWS, 128>>>(px, pt, g2 + l*DMODEL, b2 + l*DMODEL, px);

        // ---- FFN ----
        dense16(px, pwhi + F1 + l*WF, pwlo + F1 + l*WF, f1b + l*FDIM, pf,
                MROWS, FDIM, DMODEL, 256, true);
        dense16(pf, pwhi + F2 + l*WF, pwlo + F2 + l*WF, f2b + l*DMODEL, pt,
                MROWS, DMODEL, FDIM, 1024, false);
        add_ln_k<<<MROWS, 128>>>(px, pt, g3 + l*DMODEL, b3 + l*DMODEL,
                                 (l == NLAYERS-1) ? out : px);
    }
}

// round 15
// speedup vs baseline: 1.0460x; 1.0299x over previous
#include <cuda_runtime.h>
#include <cstdint>

// Problem constants
#define NLAYERS 12
#define BATCH   4
#define SEQ     1024
#define DMODEL  512
#define NHEADS  8
#define DHEAD   64
#define FDIM    2048
#define MROWS   (BATCH*SEQ)   // 4096

// ===========================================================================
// sm_80-level PTX helpers
// ===========================================================================
#define CP_ASYNC16(dst, src) \
    asm volatile("cp.async.cg.shared.global [%0], [%1], 16;" :: "r"(dst), "l"(src))
#define CP_COMMIT() asm volatile("cp.async.commit_group;" ::: "memory")
#define CP_WAIT0()  asm volatile("cp.async.wait_group 0;" ::: "memory")
#define CP_WAIT1()  asm volatile("cp.async.wait_group 1;" ::: "memory")

__device__ __forceinline__ void tf32_split(float x, uint32_t& hi, uint32_t& lo) {
    uint32_t h;
    asm("cvt.rna.tf32.f32 %0, %1;" : "=r"(h) : "f"(x));
    float r = x - __uint_as_float(h);
    uint32_t l;
    asm("cvt.rna.tf32.f32 %0, %1;" : "=r"(l) : "f"(r));
    hi = h; lo = l;
}

// Split two fp32 (k-adjacent pair) into packed bf16x2 hi and lo parts.
__device__ __forceinline__ void bf16_split2(float x0, float x1,
                                            uint32_t& hi, uint32_t& lo) {
    uint32_t h;
    asm("cvt.rn.bf16x2.f32 %0, %1, %2;" : "=r"(h) : "f"(x1), "f"(x0));
    float h0 = __uint_as_float(h << 16);
    float h1 = __uint_as_float(h & 0xffff0000u);
    float r0 = x0 - h0, r1 = x1 - h1;
    uint32_t l;
    asm("cvt.rn.bf16x2.f32 %0, %1, %2;" : "=r"(l) : "f"(r1), "f"(r0));
    hi = h; lo = l;
}

__device__ __forceinline__ void mma8(float* c, const uint32_t* a, const uint32_t* b) {
    asm volatile(
        "mma.sync.aligned.m16n8k8.row.col.f32.tf32.tf32.f32 "
        "{%0,%1,%2,%3}, {%4,%5,%6,%7}, {%8,%9}, {%0,%1,%2,%3};"
        : "+f"(c[0]), "+f"(c[1]), "+f"(c[2]), "+f"(c[3])
        : "r"(a[0]), "r"(a[1]), "r"(a[2]), "r"(a[3]), "r"(b[0]), "r"(b[1]));
}

__device__ __forceinline__ void mma16(float* c, const uint32_t* a, const uint32_t* b) {
    asm volatile(
        "mma.sync.aligned.m16n8k16.row.col.f32.bf16.bf16.f32 "
        "{%0,%1,%2,%3}, {%4,%5,%6,%7}, {%8,%9}, {%0,%1,%2,%3};"
        : "+f"(c[0]), "+f"(c[1]), "+f"(c[2]), "+f"(c[3])
        : "r"(a[0]), "r"(a[1]), "r"(a[2]), "r"(a[3]), "r"(b[0]), "r"(b[1]));
}

// ===========================================================================
// Scratch (static device globals; no allocation anywhere)
// ===========================================================================
__device__ float g_x[MROWS*DMODEL];
__device__ float g_qkv[3L*MROWS*DMODEL];     // q, k, v slabs
__device__ float g_y[MROWS*DMODEL];
__device__ float g_t[MROWS*DMODEL];
__device__ float g_f[MROWS*FDIM];
__device__ float g_ck[(long)NLAYERS*MROWS*DMODEL];   // all-layer cross K (96 MB)
__device__ float g_cv[(long)NLAYERS*MROWS*DMODEL];   // all-layer cross V (96 MB)
__device__ float g_wt[48L*DMODEL*DMODEL];    // tf32 fams transposed fp32: sq sk cq ck
// bf16 pre-split weights, packed bf16x2 along K: [fam][layer][N][K/2]
__device__ uint32_t g_whi[18874368];
__device__ uint32_t g_wlo[18874368];
__device__ float g_bias[4L*NLAYERS*DMODEL];  // packed biases (slots 0,1: sq, sk)

// ===========================================================================
// Setup kernels
// ===========================================================================
// Transpose 4 DxD tf32-path families in one launch (z = 4*12) -> fp32 [N][K]
__global__ void transpose4_k(const float* __restrict__ s0, const float* __restrict__ s1,
                             const float* __restrict__ s2, const float* __restrict__ s3,
                             float* __restrict__ dstBase)
{
    __shared__ float tt[32][33];
    const int z = blockIdx.z;
    const int f = z / NLAYERS, ly = z % NLAYERS;
    const float* S = (f == 0) ? s0 : (f == 1) ? s1 : (f == 2) ? s2 : s3;
    const long DD = (long)DMODEL*DMODEL;
    S += (long)ly * DD;
    float* D = dstBase + (long)f*NLAYERS*DD + (long)ly*DD;

    const int c0 = blockIdx.x * 32, r0 = blockIdx.y * 32;
    const int tx = threadIdx.x, ty = threadIdx.y;
    #pragma unroll
    for (int i = 0; i < 32; i += 8)
        tt[ty + i][tx] = S[(long)(r0 + ty + i)*DMODEL + c0 + tx];
    __syncthreads();
    #pragma unroll
    for (int i = 0; i < 32; i += 8)
        D[(long)(c0 + ty + i)*DMODEL + r0 + tx] = tt[tx][ty + i];
}

// Transpose + bf16-split 4 DxD bf16-path families (z = 4*12).
__global__ void tsplit4_k(const float* __restrict__ s0, const float* __restrict__ s1,
                          const float* __restrict__ s2, const float* __restrict__ s3,
                          uint32_t* __restrict__ dhi, uint32_t* __restrict__ dlo)
{
    __shared__ float tt[32][33];
    const int z = blockIdx.z;
    const int f = z / NLAYERS, ly = z % NLAYERS;
    const float* S = (f == 0) ? s0 : (f == 1) ? s1 : (f == 2) ? s2 : s3;
    S += (long)ly * DMODEL*DMODEL;
    const long obase = (long)f*NLAYERS*DMODEL*(DMODEL/2) + (long)ly*DMODEL*(DMODEL/2);
    uint32_t* DH = dhi + obase;
    uint32_t* DL = dlo + obase;

    const int k0 = blockIdx.y * 32, n0 = blockIdx.x * 32;
    const int tx = threadIdx.x, ty = threadIdx.y;
    #pragma unroll
    for (int i = 0; i < 32; i += 8)
        tt[ty + i][tx] = S[(long)(k0 + ty + i)*DMODEL + n0 + tx];
    __syncthreads();
    const int base = ty*32 + tx;
    #pragma unroll
    for (int q = 0; q < 2; q++) {
        const int o = base + q*256;
        const int nl = o >> 4, kkl = o & 15;
        uint32_t h, l;
        bf16_split2(tt[2*kkl][nl], tt[2*kkl + 1][nl], h, l);
        DH[(long)(n0 + nl)*(DMODEL/2) + (k0 >> 1) + kkl] = h;
        DL[(long)(n0 + nl)*(DMODEL/2) + (k0 >> 1) + kkl] = l;
    }
}

// Generic transpose+bf16-split (f1: R=512,C=2048; f2: R=2048,C=512)
__global__ void tsplit_k(const float* __restrict__ S, uint32_t* __restrict__ DH,
                         uint32_t* __restrict__ DL, int R, int C)
{
    __shared__ float tt[32][33];
    const long ly = blockIdx.z;
    S  += ly * (long)R * C;
    DH += ly * (long)C * (R/2);
    DL += ly * (long)C * (R/2);

    const int k0 = blockIdx.y * 32, n0 = blockIdx.x * 32;
    const int tx = threadIdx.x, ty = threadIdx.y;
    #pragma unroll
    for (int i = 0; i < 32; i += 8)
        tt[ty + i][tx] = S[(long)(k0 + ty + i)*C + n0 + tx];
    __syncthreads();
    const int base = ty*32 + tx;
    #pragma unroll
    for (int q = 0; q < 2; q++) {
        const int o = base + q*256;
        const int nl = o >> 4, kkl = o & 15;
        uint32_t h, l;
        bf16_split2(tt[2*kkl][nl], tt[2*kkl + 1][nl], h, l);
        DH[(long)(n0 + nl)*(R/2) + (k0 >> 1) + kkl] = h;
        DL[(long)(n0 + nl)*(R/2) + (k0 >> 1) + kkl] = l;
    }
}

__global__ void packbias_k(const float* __restrict__ a0, const float* __restrict__ a1,
                           const float* __restrict__ a2, const float* __restrict__ a3,
                           float* __restrict__ dst)
{
    const int i = blockIdx.x*256 + threadIdx.x;
    const int f = i / (NLAYERS*DMODEL), r = i % (NLAYERS*DMODEL);
    const float* s = (f == 0) ? a0 : (f == 1) ? a1 : (f == 2) ? a2 : a3;
    dst[i] = s[r];
}

// ===========================================================================
// tf32 GEMM — round-11 VALIDATED (in-loop splits, fp32 B, 40960 B SMEM).
// ===========================================================================
#define SMEM_D32 40960

template<bool BIAS>
__global__ __launch_bounds__(256, 1) void gemm_tf32_k(
    const float* __restrict__ A, const float* __restrict__ Bm,
    const float* __restrict__ bias, float* __restrict__ C,
    int K, int lda, int ldb, int ldc,
    long sBb, long sCb, long sbz)
{
    constexpr int AS = 20;
    constexpr int BS = 20;
    constexpr int ABUF = 128*AS;
    constexpr int BBUF = 128*BS;

    const int row0 = blockIdx.y * 128;
    const int col0 = blockIdx.x * 128;
    const int zb = blockIdx.z;
    Bm += (long)zb*sBb;
    C  += (long)zb*sCb;
    if (BIAS) bias += (long)zb*sbz;

    extern __shared__ float smf[];
    float* Asm = smf;
    float* Bsm = smf + 2*ABUF;

    const int tid  = threadIdx.x;
    const int wid  = tid >> 5;
    const int lane = tid & 31;
    const int g = lane >> 2, t = lane & 3;
    const int wm = (wid >> 2) * 64;
    const int wn = (wid & 3) * 32;

    const int ns = K >> 4;

    auto loadA = [&](int s) {
        float* dst = Asm + (s & 1) * ABUF;
        const int r  = tid >> 1;
        const int kc = (tid & 1) << 3;
        uint32_t d = (uint32_t)__cvta_generic_to_shared(dst + r*AS + kc);
        CP_ASYNC16(d, A + (long)(row0 + r)*lda + (s << 4) + kc);
        uint32_t d2 = (uint32_t)__cvta_generic_to_shared(dst + r*AS + kc + 4);
        CP_ASYNC16(d2, A + (long)(row0 + r)*lda + (s << 4) + kc + 4);
    };
    auto loadB = [&](int s) {
        float* dst = Bsm + (s & 1) * BBUF;
        const int r  = tid >> 1;
        const int kc = (tid & 1) << 3;
        uint32_t d = (uint32_t)__cvta_generic_to_shared(dst + r*BS + kc);
        CP_ASYNC16(d, Bm + (long)(col0 + r)*ldb + (s << 4) + kc);
        uint32_t d2 = (uint32_t)__cvta_generic_to_shared(dst + r*BS + kc + 4);
        CP_ASYNC16(d2, Bm + (long)(col0 + r)*ldb + (s << 4) + kc + 4);
    };

    float acc[4][4][4] = {};

    loadA(0); loadB(0); CP_COMMIT();

    for (int s = 0; s < ns; s++) {
        if (s + 1 < ns) { loadA(s+1); loadB(s+1); CP_COMMIT(); CP_WAIT1(); }
        else            { CP_WAIT0(); }
        __syncthreads();

        const float* a = Asm + (s & 1) * ABUF;
        const float* b = Bsm + (s & 1) * BBUF;

        #pragma unroll
        for (int kk = 0; kk < 16; kk += 8) {
            uint32_t ahi[4][4], alo[4][4];
            #pragma unroll
            for (int i = 0; i < 4; i++) {
                const int m0 = wm + 16*i + g;
                tf32_split(a[(m0    )*AS + kk + t    ], ahi[i][0], alo[i][0]);
                tf32_split(a[(m0 + 8)*AS + kk + t    ], ahi[i][1], alo[i][1]);
                tf32_split(a[(m0    )*AS + kk + t + 4], ahi[i][2], alo[i][2]);
                tf32_split(a[(m0 + 8)*AS + kk + t + 4], ahi[i][3], alo[i][3]);
            }
            #pragma unroll
            for (int j = 0; j < 4; j++) {
                const int n0 = wn + 8*j + g;
                uint32_t bhi[2], blo[2];
                tf32_split(b[n0*BS + kk + t    ], bhi[0], blo[0]);
                tf32_split(b[n0*BS + kk + t + 4], bhi[1], blo[1]);
                #pragma unroll
                for (int i = 0; i < 4; i++) {
                    mma8(acc[i][j], ahi[i], bhi);
                    mma8(acc[i][j], ahi[i], blo);
                    mma8(acc[i][j], alo[i], bhi);
                }
            }
        }
        __syncthreads();
    }

    #pragma unroll
    for (int j = 0; j < 4; j++) {
        const int cb = col0 + wn + 8*j + 2*t;
        float bx = 0.f, by = 0.f;
        if (BIAS) { bx = bias[cb]; by = bias[cb + 1]; }
        #pragma unroll
        for (int i = 0; i < 4; i++) {
            const int r = row0 + wm + 16*i + g;
            float2 v0, v1;
            v0.x = acc[i][j][0] + bx; v0.y = acc[i][j][1] + by;
            v1.x = acc[i][j][2] + bx; v1.y = acc[i][j][3] + by;
            *(float2*)&C[(long)r*ldc + cb]       = v0;
            *(float2*)&C[(long)(r + 8)*ldc + cb] = v1;
        }
    }
}

// ===========================================================================
// bf16 GEMM v2 — round-11 VALIDATED + z-batch plumbing (zb offsets only).
// ===========================================================================
#define SMEM_B16 57344

template<bool BIAS, bool RELU>
__global__ __launch_bounds__(256, 1) void gemm_bf16_k(
    const float* __restrict__ A, const uint32_t* __restrict__ Whi,
    const uint32_t* __restrict__ Wlo, const float* __restrict__ bias,
    float* __restrict__ C, int K, int lda, int ldw, int ldc,
    long sBb, long sCb, long sbz)
{
    constexpr int AS = 20;
    constexpr int WS = 12;

    const int row0 = blockIdx.y * 128;
    const int col0 = blockIdx.x * 128;
    const int zb = blockIdx.z;
    Whi += (long)zb*sBb;
    Wlo += (long)zb*sBb;
    C   += (long)zb*sCb;
    if (BIAS) bias += (long)zb*sbz;

    extern __shared__ float smf[];
    float*    Asm = smf;                          // 2 * 2560
    uint32_t* AH  = (uint32_t*)(smf + 5120);      // 1536
    uint32_t* AL  = (uint32_t*)(smf + 6656);      // 1536
    uint32_t* BH  = (uint32_t*)(smf + 8192);      // 2 * 1536
    uint32_t* BL  = (uint32_t*)(smf + 11264);     // 2 * 1536

    const int tid  = threadIdx.x;
    const int wid  = tid >> 5;
    const int lane = tid & 31;
    const int g = lane >> 2, t = lane & 3;
    const int wm = (wid >> 2) * 64;
    const int wn = (wid & 3) * 32;

    const int ns = K >> 4;

    auto loadA = [&](int s) {
        float* dst = Asm + (s & 1) * 2560;
        const int r  = tid >> 1;
        const int kc = (tid & 1) << 3;
        uint32_t d = (uint32_t)__cvta_generic_to_shared(dst + r*AS + kc);
        CP_ASYNC16(d, A + (long)(row0 + r)*lda + (s << 4) + kc);
        uint32_t d2 = (uint32_t)__cvta_generic_to_shared(dst + r*AS + kc + 4);
        CP_ASYNC16(d2, A + (long)(row0 + r)*lda + (s << 4) + kc + 4);
    };
    auto loadB = [&](int s) {
        uint32_t* dh = BH + (s & 1) * 1536;
        uint32_t* dl = BL + (s & 1) * 1536;
        const int r = tid >> 1, half = (tid & 1) << 2;
        uint32_t d = (uint32_t)__cvta_generic_to_shared(dh + r*WS + half);
        CP_ASYNC16(d, Whi + (long)(col0 + r)*ldw + (s << 3) + half);
        uint32_t d2 = (uint32_t)__cvta_generic_to_shared(dl + r*WS + half);
        CP_ASYNC16(d2, Wlo + (long)(col0 + r)*ldw + (s << 3) + half);
    };

    float acc[4][4][4] = {};

    loadA(0); loadB(0); CP_COMMIT();

    for (int s = 0; s < ns; s++) {
        if (s + 1 < ns) { loadA(s+1); loadB(s+1); CP_COMMIT(); CP_WAIT1(); }
        else            { CP_WAIT0(); }
        __syncthreads();

        {
            const float* a = Asm + (s & 1) * 2560;
            #pragma unroll
            for (int p2 = 0; p2 < 4; p2++) {
                const int p = tid + (p2 << 8);
                const int r = p >> 3, c2 = p & 7;
                float2 x = *(const float2*)&a[r*AS + 2*c2];
                uint32_t h, l;
                bf16_split2(x.x, x.y, h, l);
                AH[r*WS + c2] = h;
                AL[r*WS + c2] = l;
            }
        }
        __syncthreads();

        const uint32_t* bh = BH + (s & 1) * 1536;
        const uint32_t* bl = BL + (s & 1) * 1536;

        uint32_t ahi[4][4], alo[4][4];
        #pragma unroll
        for (int i = 0; i < 4; i++) {
            #pragma unroll
            for (int rr = 0; rr < 4; rr++) {
                const int r  = wm + 16*i + g + 8*(rr & 1);
                const int cc = t + 4*(rr >> 1);
                ahi[i][rr] = AH[r*WS + cc];
                alo[i][rr] = AL[r*WS + cc];
            }
        }
        #pragma unroll
        for (int j = 0; j < 4; j++) {
            const int n0 = wn + 8*j + g;
            uint32_t bhi[2], blo[2];
            bhi[0] = bh[n0*WS + t];     bhi[1] = bh[n0*WS + t + 4];
            blo[0] = bl[n0*WS + t];     blo[1] = bl[n0*WS + t + 4];
            #pragma unroll
            for (int i = 0; i < 4; i++) {
                mma16(acc[i][j], ahi[i], bhi);
                mma16(acc[i][j], ahi[i], blo);
                mma16(acc[i][j], alo[i], bhi);
            }
        }
        __syncthreads();
    }

    #pragma unroll
    for (int j = 0; j < 4; j++) {
        const int cb = col0 + wn + 8*j + 2*t;
        float bx = 0.f, by = 0.f;
        if (BIAS) { bx = bias[cb]; by = bias[cb + 1]; }
        #pragma unroll
        for (int i = 0; i < 4; i++) {
            const int r = row0 + wm + 16*i + g;
            float2 v0, v1;
            v0.x = acc[i][j][0] + bx; v0.y = acc[i][j][1] + by;
            v1.x = acc[i][j][2] + bx; v1.y = acc[i][j][3] + by;
            if (RELU) {
                v0.x = fmaxf(v0.x, 0.f); v0.y = fmaxf(v0.y, 0.f);
                v1.x = fmaxf(v1.x, 0.f); v1.y = fmaxf(v1.y, 0.f);
            }
            *(float2*)&C[(long)r*ldc + cb]       = v0;
            *(float2*)&C[(long)(r + 8)*ldc + cb] = v1;
        }
    }
}

// ===========================================================================
// Flash attention v3 — round-11 VALIDATED, unchanged.
// ===========================================================================
#define TSF 68
#define PST 66
#define FLASH_SMEM 210944

template<bool CAUSAL>
__global__ __launch_bounds__(256, 1) void flash_k(
    const float* __restrict__ Qg, const float* __restrict__ Kg,
    const float* __restrict__ Vg, float* __restrict__ Yg)
{
    extern __shared__ float sm[];
    constexpr int QHOFF = 0;
    constexpr int QLOFF = 128*TSF;
    constexpr int KOFF  = 2*128*TSF;
    constexpr int VOFF  = 3*128*TSF;
    constexpr int POFF  = 4*128*TSF;
    constexpr int RMOFF = POFF + 128*PST*2;
    constexpr int RSOFF = RMOFF + 512;

    const int qb = blockIdx.x;
    const int bh = blockIdx.y;
    const long base = ((long)(bh >> 3)*SEQ)*DMODEL + (bh & 7)*DHEAD;
    const float* Kp = Kg + base;
    const float* Vp = Vg + base;

    const int tid = threadIdx.x;
    const int wid = tid >> 5, lane = tid & 31;
    const int g = lane >> 2, t = lane & 3;
    const int wy = wid >> 2, wx = wid & 3;

    const int nb = CAUSAL ? (qb + 1) : (SEQ/128);

    auto load_tile = [&](int off, const float* src) {
        #pragma unroll
        for (int it = 0; it < 8; it++) {
            const int idx = tid + (it << 8);
            const int r = idx >> 4, c = (idx & 15) << 2;
            uint32_t d = (uint32_t)__cvta_generic_to_shared(sm + off + r*TSF + c);
            CP_ASYNC16(d, src + (long)r*DMODEL + c);
        }
    };

    load_tile(KOFF, Qg + base + (long)qb*128*DMODEL);
    CP_COMMIT(); CP_WAIT0();
    __syncthreads();
    {
        uint32_t* QH = (uint32_t*)(sm + QHOFF);
        uint32_t* QL = (uint32_t*)(sm + QLOFF);
        const float* qsrc = sm + KOFF;
        #pragma unroll
        for (int i2 = 0; i2 < 32; i2++) {
            const int p = tid + (i2 << 8);
            const int r = p >> 6, c = p & 63;
            uint32_t h, l;
            tf32_split(qsrc[r*TSF + c], h, l);
            QH[r*TSF + c] = h;
            QL[r*TSF + c] = l;
        }
    }
    __syncthreads();

    const uint32_t* QH = (const uint32_t*)(sm + QHOFF);
    const uint32_t* QL = (const uint32_t*)(sm + QLOFF);

    float m[8], l[8];
    #pragma unroll
    for (int s = 0; s < 8; s++) { m[s] = -1e30f; l[s] = 0.f; }
    float accO[4][2][4] = {};

    uint2* Pp = (uint2*)(sm + POFF);

    for (int n = 0; n < nb; n++) {
        __syncthreads();
        load_tile(KOFF, Kp + (long)n*128*DMODEL);
        load_tile(VOFF, Vp + (long)n*128*DMODEL);
        CP_COMMIT(); CP_WAIT0();
        __syncthreads();

        float accS[4][4][4] = {};
        #pragma unroll
        for (int kk = 0; kk < 64; kk += 8) {
            uint32_t ahi[4][4], alo[4][4];
            #pragma unroll
            for (int i = 0; i < 4; i++) {
                const int mb = wy*64 + 16*i + g;
                ahi[i][0] = QH[(mb    )*TSF + kk + t    ];
                ahi[i][1] = QH[(mb + 8)*TSF + kk + t    ];
                ahi[i][2] = QH[(mb    )*TSF + kk + t + 4];
                ahi[i][3] = QH[(mb + 8)*TSF + kk + t + 4];
                alo[i][0] = QL[(mb    )*TSF + kk + t    ];
                alo[i][1] = QL[(mb + 8)*TSF + kk + t    ];
                alo[i][2] = QL[(mb    )*TSF + kk + t + 4];
                alo[i][3] = QL[(mb + 8)*TSF + kk + t + 4];
            }
            #pragma unroll
            for (int j = 0; j < 4; j++) {
                const int n0 = wx*32 + 8*j + g;
                uint32_t bhi[2], blo[2];
                tf32_split(sm[KOFF + n0*TSF + kk + t    ], bhi[0], blo[0]);
                tf32_split(sm[KOFF + n0*TSF + kk + t + 4], bhi[1], blo[1]);
                #pragma unroll
                for (int i = 0; i < 4; i++) {
                    mma8(accS[i][j], ahi[i], bhi);
                    mma8(accS[i][j], ahi[i], blo);
                    mma8(accS[i][j], alo[i], bhi);
                }
            }
        }

        if (CAUSAL && n == qb) {
            #pragma unroll
            for (int i = 0; i < 4; i++) {
                const int r0 = wy*64 + 16*i + g;
                #pragma unroll
                for (int j = 0; j < 4; j++) {
                    const int c0 = wx*32 + 8*j + 2*t;
                    if (c0     > r0    ) accS[i][j][0] = -1e30f;
                    if (c0 + 1 > r0    ) accS[i][j][1] = -1e30f;
                    if (c0     > r0 + 8) accS[i][j][2] = -1e30f;
                    if (c0 + 1 > r0 + 8) accS[i][j][3] = -1e30f;
                }
            }
        }

        #pragma unroll
        for (int i = 0; i < 4; i++) {
            #pragma unroll
            for (int rh = 0; rh < 2; rh++) {
                float pm = -1e30f;
                #pragma unroll
                for (int j = 0; j < 4; j++)
                    pm = fmaxf(pm, fmaxf(accS[i][j][2*rh], accS[i][j][2*rh+1]));
                pm = fmaxf(pm, __shfl_xor_sync(0xffffffffu, pm, 1));
                pm = fmaxf(pm, __shfl_xor_sync(0xffffffffu, pm, 2));
                if (t == 0) sm[RMOFF + (wy*64 + 16*i + g + 8*rh)*4 + wx] = pm;
            }
        }
        __syncthreads();

        #pragma unroll
        for (int i = 0; i < 4; i++) {
            #pragma unroll
            for (int rh = 0; rh < 2; rh++) {
                const int s = 2*i + rh;
                const int row = wy*64 + 16*i + g + 8*rh;
                const float* rm = sm + RMOFF + row*4;
                float bm = fmaxf(fmaxf(rm[0], rm[1]), fmaxf(rm[2], rm[3]));
                float mnew = fmaxf(m[s], bm);
                float alpha = __expf((m[s] - mnew) * 0.125f);
                m[s] = mnew;
                l[s] *= alpha;
                #pragma unroll
                for (int j2 = 0; j2 < 2; j2++) {
                    accO[i][j2][2*rh  ] *= alpha;
                    accO[i][j2][2*rh+1] *= alpha;
                }
                float ps = 0.f;
                #pragma unroll
                for (int j = 0; j < 4; j++) {
                    float e0 = __expf((accS[i][j][2*rh  ] - mnew) * 0.125f);
                    float e1 = __expf((accS[i][j][2*rh+1] - mnew) * 0.125f);
                    ps += e0 + e1;
                    uint32_t hi, lo;
                    bf16_split2(e0, e1, hi, lo);
                    Pp[row*PST + wx*16 + 4*j + t] = make_uint2(hi, lo);
                }
                ps += __shfl_xor_sync(0xffffffffu, ps, 1);
                ps += __shfl_xor_sync(0xffffffffu, ps, 2);
                if (t == 0) sm[RSOFF + row*4 + wx] = ps;
            }
        }
        __syncthreads();

        #pragma unroll
        for (int i = 0; i < 4; i++)
            #pragma unroll
            for (int rh = 0; rh < 2; rh++) {
                const int row = wy*64 + 16*i + g + 8*rh;
                const float* rs = sm + RSOFF + row*4;
                l[2*i + rh] += rs[0] + rs[1] + rs[2] + rs[3];
            }

        #pragma unroll
        for (int kt = 0; kt < 8; kt++) {
            uint32_t pahi[4][4], palo[4][4];
            #pragma unroll
            for (int i = 0; i < 4; i++) {
                #pragma unroll
                for (int rr = 0; rr < 4; rr++) {
                    const int r  = wy*64 + 16*i + g + 8*(rr & 1);
                    const int kp = kt*8 + t + 4*(rr >> 1);
                    uint2 hl = Pp[r*PST + kp];
                    pahi[i][rr] = hl.x; palo[i][rr] = hl.y;
                }
            }
            #pragma unroll
            for (int j2 = 0; j2 < 2; j2++) {
                const int n0 = wx*16 + 8*j2 + g;
                uint32_t vh[2], vl[2];
                #pragma unroll
                for (int rr = 0; rr < 2; rr++) {
                    const int kc = kt*16 + 2*t + 8*rr;
                    bf16_split2(sm[VOFF + kc*TSF + n0], sm[VOFF + (kc+1)*TSF + n0],
                                vh[rr], vl[rr]);
                }
                #pragma unroll
                for (int i = 0; i < 4; i++) {
                    mma16(accO[i][j2], pahi[i], vh);
                    mma16(accO[i][j2], pahi[i], vl);
                    mma16(accO[i][j2], palo[i], vh);
                }
            }
        }
    }

    #pragma unroll
    for (int i = 0; i < 4; i++) {
        #pragma unroll
        for (int rh = 0; rh < 2; rh++) {
            const int row = wy*64 + 16*i + g + 8*rh;
            const float inv = 1.f / l[2*i + rh];
            #pragma unroll
            for (int j2 = 0; j2 < 2; j2++) {
                float2 v;
                v.x = accO[i][j2][2*rh  ] * inv;
                v.y = accO[i][j2][2*rh+1] * inv;
                *(float2*)&Yg[base + (long)(qb*128 + row)*DMODEL + wx*16 + 8*j2 + 2*t] = v;
            }
        }
    }
}

// ===========================================================================
// LayerNorm / pos-add
// ===========================================================================
__global__ void add_ln_k(const float* __restrict__ X, const float* __restrict__ Y,
                         const float* __restrict__ g, const float* __restrict__ b,
                         float* __restrict__ O)
{
    const long row = blockIdx.x;
    const float* x = X + row * DMODEL;
    const float* y = Y + row * DMODEL;
    float* o = O + row * DMODEL;
    const int t = threadIdx.x;
    __shared__ float sm[4];

    float v[4];
    float s = 0.f;
    #pragma unroll
    for (int i = 0; i < 4; i++) {
        int j = t + i*128;
        v[i] = x[j] + y[j];
        s += v[i];
    }
    #pragma unroll
    for (int o2 = 16; o2 > 0; o2 >>= 1) s += __shfl_xor_sync(0xffffffffu, s, o2);
    if ((t & 31) == 0) sm[t >> 5] = s;
    __syncthreads();
    const float mu = (sm[0]+sm[1]+sm[2]+sm[3]) * (1.f/DMODEL);
    __syncthreads();
    float var = 0.f;
    #pragma unroll
    for (int i = 0; i < 4; i++) { float d = v[i]-mu; var += d*d; }
    #pragma unroll
    for (int o2 = 16; o2 > 0; o2 >>= 1) var += __shfl_xor_sync(0xffffffffu, var, o2);
    if ((t & 31) == 0) sm[t >> 5] = var;
    __syncthreads();
    const float rs = rsqrtf((sm[0]+sm[1]+sm[2]+sm[3]) * (1.f/DMODEL) + 1e-5f);
    #pragma unroll
    for (int i = 0; i < 4; i++) {
        int j = t + i*128;
        o[j] = (v[i]-mu)*rs*g[j] + b[j];
    }
}

__global__ void addpos_k(const float* __restrict__ x, const float* __restrict__ pos,
                         float* __restrict__ o)
{
    long idx = (long)blockIdx.x * 256 + threadIdx.x;
    long sd  = idx % ((long)SEQ * DMODEL);
    o[idx] = x[idx] + pos[sd];
}

// ===========================================================================
// Host-side launch helpers
// ===========================================================================
static void dense32(const float* A, const float* Bt, const float* bias, float* C,
                    int M, int N, int K, long sBb, long sCb, long sbz, int nz)
{
    dim3 grid(N/128, M/128, nz);
    gemm_tf32_k<true><<<grid,256,SMEM_D32>>>(A,Bt,bias,C,K, K,K,N, sBb,sCb,sbz);
}
static void dense16(const float* A, const uint32_t* Whi, const uint32_t* Wlo,
                    const float* bias, float* C, int M, int N, int K, int ldw,
                    bool relu, long sBb = 0, long sCb = 0, long sbz = 0, int nz = 1)
{
    dim3 grid(N/128, M/128, nz);
    if (relu)
        gemm_bf16_k<true,true ><<<grid,256,SMEM_B16>>>(A,Whi,Wlo,bias,C,K, K,ldw,N, sBb,sCb,sbz);
    else
        gemm_bf16_k<true,false><<<grid,256,SMEM_B16>>>(A,Whi,Wlo,bias,C,K, K,ldw,N, sBb,sCb,sbz);
}

extern "C" void kernel_launch(void* const* d_in, const int* in_sizes, int n_in,
                              void* d_out, int out_size)
{
    const float* kv   = (const float*)d_in[0];
    const float* xin  = (const float*)d_in[1];
    const float* pos  = (const float*)d_in[2];
    const float* sqW  = (const float*)d_in[3];  const float* sqb = (const float*)d_in[4];
    const float* skW  = (const float*)d_in[5];  const float* skb = (const float*)d_in[6];
    const float* svW  = (const float*)d_in[7];  const float* svb = (const float*)d_in[8];
    const float* soW  = (const float*)d_in[9];  const float* sob = (const float*)d_in[10];
    const float* cqW  = (const float*)d_in[11]; const float* cqb = (const float*)d_in[12];
    const float* ckW  = (const float*)d_in[13]; const float* ckb = (const float*)d_in[14];
    const float* cvW  = (const float*)d_in[15]; const float* cvb = (const float*)d_in[16];
    const float* coW  = (const float*)d_in[17]; const float* cob = (const float*)d_in[18];
    const float* f1W  = (const float*)d_in[19]; const float* f1b = (const float*)d_in[20];
    const float* f2W  = (const float*)d_in[21]; const float* f2b = (const float*)d_in[22];
    const float* g1   = (const float*)d_in[23]; const float* b1  = (const float*)d_in[24];
    const float* g2   = (const float*)d_in[25]; const float* b2  = (const float*)d_in[26];
    const float* g3   = (const float*)d_in[27]; const float* b3  = (const float*)d_in[28];
    float* out = (float*)d_out;

    cudaFuncSetAttribute(gemm_tf32_k<true>, cudaFuncAttributeMaxDynamicSharedMemorySize, SMEM_D32);
    cudaFuncSetAttribute(gemm_bf16_k<true,false>, cudaFuncAttributeMaxDynamicSharedMemorySize, SMEM_B16);
    cudaFuncSetAttribute(gemm_bf16_k<true,true >, cudaFuncAttributeMaxDynamicSharedMemorySize, SMEM_B16);
    cudaFuncSetAttribute(flash_k<true >, cudaFuncAttributeMaxDynamicSharedMemorySize, FLASH_SMEM);
    cudaFuncSetAttribute(flash_k<false>, cudaFuncAttributeMaxDynamicSharedMemorySize, FLASH_SMEM);

    float *px,*pqkv,*py,*pt,*pf,*pck,*pcv,*pwt,*pbias;
    uint32_t *pwhi,*pwlo;
    cudaGetSymbolAddress((void**)&px, g_x);
    cudaGetSymbolAddress((void**)&pqkv, g_qkv);
    cudaGetSymbolAddress((void**)&py, g_y);
    cudaGetSymbolAddress((void**)&pt, g_t);
    cudaGetSymbolAddress((void**)&pf, g_f);
    cudaGetSymbolAddress((void**)&pck, g_ck);
    cudaGetSymbolAddress((void**)&pcv, g_cv);
    cudaGetSymbolAddress((void**)&pwt, g_wt);
    cudaGetSymbolAddress((void**)&pwhi, g_whi);
    cudaGetSymbolAddress((void**)&pwlo, g_wlo);
    cudaGetSymbolAddress((void**)&pbias, g_bias);

    const long DD = (long)DMODEL*DMODEL;
    const long MD = (long)MROWS*DMODEL;

    float* pq = pqkv;
    float* pk = pqkv + MD;
    float* pv = pqkv + 2*MD;

    // tf32 transposed fams in g_wt: sq@0, sk@12DD, cq@24DD, ck@36DD
    float* sqT = pwt;
    float* cqT = pwt + 24*DD;
    float* ckT = pwt + 36*DD;

    // bf16 pre-split fams in g_whi/g_wlo (uint32 offsets)
    const long WDD = 131072;   // 512*256 per layer
    const long WF  = 524288;
    const long SV = 0, SO = 12*WDD, CV = 24*WDD, CO = 36*WDD;
    const long F1 = 48*WDD, F2 = F1 + 12*WF;

    {
        dim3 blk(32, 8);
        transpose4_k<<<dim3(16,16,4*NLAYERS), blk>>>(sqW, skW, cqW, ckW, pwt);
        tsplit4_k<<<dim3(16,16,4*NLAYERS), blk>>>(svW, soW, cvW, coW, pwhi, pwlo);
        tsplit_k<<<dim3(64,16,NLAYERS), blk>>>(f1W, pwhi + F1, pwlo + F1, DMODEL, FDIM);
        tsplit_k<<<dim3(16,64,NLAYERS), blk>>>(f2W, pwhi + F2, pwlo + F2, FDIM, DMODEL);
        packbias_k<<<(4*NLAYERS*DMODEL)/256, 256>>>(sqb, skb, sqb, sqb, pbias);
    }

    // Hoisted: cross K and V for ALL layers (kv is layer-invariant).
    dense32(kv, ckT, ckb, pck, MROWS, DMODEL, DMODEL, DD, MD, DMODEL, NLAYERS);
    dense16(kv, pwhi + CV, pwlo + CV, cvb, pcv, MROWS, DMODEL, DMODEL, 256,
            false, WDD, MD, DMODEL, NLAYERS);

    addpos_k<<<(MROWS*DMODEL)/256, 256>>>(xin, pos, px);

    const long LB = (long)NLAYERS*DMODEL;
    const dim3 fgrid(SEQ/128, BATCH*NHEADS);

    for (int l = 0; l < NLAYERS; l++) {
        // ---- self-attention (causal) ----
        dense32(px, sqT + l*DD, pbias + l*DMODEL, pq,
                MROWS, DMODEL, DMODEL, 12*DD, MD, LB, 2);      // Q and K batched
        dense16(px, pwhi + SV + l*WDD, pwlo + SV + l*WDD, svb + l*DMODEL, pv,
                MROWS, DMODEL, DMODEL, 256, false);
        flash_k<true ><<<fgrid, 256, FLASH_SMEM>>>(pq, pk, pv, py);
        dense16(py, pwhi + SO + l*WDD, pwlo + SO + l*WDD, sob + l*DMODEL, pt,
                MROWS, DMODEL, DMODEL, 256, false);
        add_ln_k<<<MROWS, 128>>>(px, pt, g1 + l*DMODEL, b1 + l*DMODEL, px);

        // ---- cross-attention (K/V precomputed) ----
        dense32(px, cqT + l*DD, cqb + l*DMODEL, pq, MROWS, DMODEL, DMODEL, 0, 0, 0, 1);
        flash_k<false><<<fgrid, 256, FLASH_SMEM>>>(pq, pck + l*MD, pcv + l*MD, py);
        dense16(py, pwhi + CO + l*WDD, pwlo + CO + l*WDD, cob + l*DMODEL, pt,
                MROWS, DMODEL, DMODEL, 256, false);
        add_ln_k<<<MROWS, 128>>>(px, pt, g2 + l*DMODEL, b2 + l*DMODEL, px);

        // ---- FFN ----
        dense16(px, pwhi + F1 + l*WF, pwlo + F1 + l*WF, f1b + l*FDIM, pf,
                MROWS, FDIM, DMODEL, 256, true);
        dense16(pf, pwhi + F2 + l*WF, pwlo + F2 + l*WF, f2b + l*DMODEL, pt,
                MROWS, DMODEL, FDIM, 1024, false);
        add_ln_k<<<MROWS, 128>>>(px, pt, g3 + l*DMODEL, b3 + l*DMODEL,
                                 (l == NLAYERS-1) ? out : px);
    }
}